// round 4
// baseline (speedup 1.0000x reference)
#include <cuda_runtime.h>

// ---------------------------------------------------------------------------
// Problem constants
// ---------------------------------------------------------------------------
#define NH    4          // heads
#define CH    64         // channels per head
#define HC    256        // NH*CH
#define NIN   300
#define NOUT  768
#define MAXN  50048
#define MAXG  1024
#define SLOPE_ATT 0.2f
#define SLOPE_ACT 0.01f

// ---------------------------------------------------------------------------
// Scratch (device globals; no allocation allowed)
// ---------------------------------------------------------------------------
__device__ float g_h[MAXN * HC];       // node features after lin  [N, HC]
__device__ float g_o[MAXN * HC];       // weighted aggregation     [N, HC]
__device__ float g_asrc[MAXN * NH];
__device__ float g_adst[MAXN * NH];
__device__ float g_den[MAXN * NH];     // softmax denom (no max-shift needed)
__device__ float g_pool[MAXG * HC];
__device__ float g_cnt[MAXG];

// ---------------------------------------------------------------------------
// Helpers
// ---------------------------------------------------------------------------
__device__ __forceinline__ float lrelu(float v, float s) { return v > 0.0f ? v : s * v; }

__device__ __forceinline__ unsigned long long pack2(float lo, float hi) {
    unsigned long long r;
    asm("mov.b64 %0, {%1, %2};" : "=l"(r) : "f"(lo), "f"(hi));
    return r;
}
__device__ __forceinline__ float2 unpack2(unsigned long long v) {
    float2 f;
    asm("mov.b64 {%0, %1}, %2;" : "=f"(f.x), "=f"(f.y) : "l"(v));
    return f;
}
// packed dual-FMA: acc(2xf32) += a(2xf32) * b(2xf32)   (sm_100+)
__device__ __forceinline__ void ffma2(unsigned long long& acc,
                                      unsigned long long a, unsigned long long b) {
    asm("fma.rn.f32x2 %0, %1, %2, %0;" : "+l"(acc) : "l"(a), "l"(b));
}
__device__ __forceinline__ void red_add_v4(float* p, float4 v) {
    asm volatile("red.global.add.v4.f32 [%0], {%1, %2, %3, %4};"
                 :: "l"(p), "f"(v.x), "f"(v.y), "f"(v.z), "f"(v.w) : "memory");
}

// ---------------------------------------------------------------------------
// K1: fused  h = x @ lin_w ;  a_src/a_dst ;  self-loop init of den & o
// Tile: 64 rows x 256 cols (full channel width per block), BK=8, 256 threads,
// 8x8 micro-tile on f32x2 FMAs. Epilogue computes per-head attention dots via
// 8-lane shuffles and writes g_h, g_o = h*ee_self, g_den = ee_self.
// ---------------------------------------------------------------------------
__global__ void __launch_bounds__(256, 1) k_gemm_fused(const float* __restrict__ x,
                                                       const float* __restrict__ w,
                                                       const float* __restrict__ att_src,
                                                       const float* __restrict__ att_dst,
                                                       int Ntot) {
    __shared__ float As[8][64];
    __shared__ float Bs[8][256];

    const int t  = threadIdx.x;
    const int m0 = blockIdx.x * 64;
    const int tx = t & 31;           // col-group: cols tx*8 .. tx*8+7  (lane id)
    const int ty = t >> 5;           // row-group: rows ty*8 .. ty*8+7  (warp id)

    // A-load mapping: threads 0..127 load one float4 each (64 rows x 8 k)
    const int lm = t >> 1;           // row within tile (0..63 for t<128)
    const int lv = t & 1;            // k sub-quad
    // B-load mapping: each thread loads 2 float4 (8 k x 256 cols = 512 float4)

    unsigned long long acc[8][4];
#pragma unroll
    for (int i = 0; i < 8; i++)
#pragma unroll
        for (int j = 0; j < 4; j++) acc[i][j] = 0ull;

    const int nk = (NIN + 7) / 8;    // 38

    float4 ra, rb0, rb1;
    // prefetch tile 0
    {
        ra = make_float4(0.f, 0.f, 0.f, 0.f);
        if (t < 128) {
            const int m = m0 + lm;
            const int k = lv * 4;
            if (m < Ntot && k < NIN)   // k=0 or 4, both < 300
                ra = *(const float4*)(x + (size_t)m * NIN + k);
        }
        const int i0 = t,      k0b = i0 >> 6, c0 = i0 & 63;
        const int i1 = t + 256, k1b = i1 >> 6, c1 = i1 & 63;
        rb0 = *(const float4*)(w + (size_t)k0b * HC + c0 * 4);
        rb1 = *(const float4*)(w + (size_t)k1b * HC + c1 * 4);
    }

    for (int kt = 0; kt < nk; kt++) {
        __syncthreads();
        if (t < 128) {
            As[lv * 4 + 0][lm] = ra.x;
            As[lv * 4 + 1][lm] = ra.y;
            As[lv * 4 + 2][lm] = ra.z;
            As[lv * 4 + 3][lm] = ra.w;
        }
        {
            const int i0 = t,      k0b = i0 >> 6, c0 = i0 & 63;
            const int i1 = t + 256, k1b = i1 >> 6, c1 = i1 & 63;
            ((float4*)&Bs[k0b][0])[c0] = rb0;
            ((float4*)&Bs[k1b][0])[c1] = rb1;
        }
        __syncthreads();

        // prefetch next tile
        if (kt + 1 < nk) {
            const int kbase = (kt + 1) * 8;
            ra = make_float4(0.f, 0.f, 0.f, 0.f);
            if (t < 128) {
                const int m  = m0 + lm;
                const int ka = kbase + lv * 4;
                if (m < Ntot && ka < NIN)   // ka+3 <= 299 always when ka<300 (300%4==0)
                    ra = *(const float4*)(x + (size_t)m * NIN + ka);
            }
            const int i0 = t,      c0 = i0 & 63;
            const int i1 = t + 256, c1 = i1 & 63;
            const int kb0 = kbase + (i0 >> 6);
            const int kb1 = kbase + (i1 >> 6);
            rb0 = make_float4(0.f, 0.f, 0.f, 0.f);
            rb1 = make_float4(0.f, 0.f, 0.f, 0.f);
            if (kb0 < NIN) rb0 = *(const float4*)(w + (size_t)kb0 * HC + c0 * 4);
            if (kb1 < NIN) rb1 = *(const float4*)(w + (size_t)kb1 * HC + c1 * 4);
        }

        // compute
#pragma unroll
        for (int k = 0; k < 8; k++) {
            float4 a0 = *(const float4*)&As[k][ty * 8];
            float4 a1 = *(const float4*)&As[k][ty * 8 + 4];
            float4 b0 = *(const float4*)&Bs[k][tx * 8];
            float4 b1 = *(const float4*)&Bs[k][tx * 8 + 4];
            unsigned long long bp[4] = {pack2(b0.x, b0.y), pack2(b0.z, b0.w),
                                        pack2(b1.x, b1.y), pack2(b1.z, b1.w)};
            float am[8] = {a0.x, a0.y, a0.z, a0.w, a1.x, a1.y, a1.z, a1.w};
#pragma unroll
            for (int i = 0; i < 8; i++) {
                unsigned long long ap = pack2(am[i], am[i]);
#pragma unroll
                for (int j = 0; j < 4; j++) ffma2(acc[i][j], ap, bp[j]);
            }
        }
    }

    // ---------------- fused epilogue ----------------
    // This thread owns cols [tx*8, tx*8+8) of rows [m0+ty*8, +8).
    // All cols are within head = tx>>3 (head boundary = 64 = multiple of 8 lanes).
    const int cbase = tx * 8;
    const int head  = tx >> 3;
    const float4* sp = (const float4*)(att_src + cbase);
    const float4* dp = (const float4*)(att_dst + cbase);
    float4 s0 = sp[0], s1 = sp[1];
    float4 d0 = dp[0], d1 = dp[1];

#pragma unroll
    for (int i = 0; i < 8; i++) {
        float2 c01 = unpack2(acc[i][0]);
        float2 c23 = unpack2(acc[i][1]);
        float2 c45 = unpack2(acc[i][2]);
        float2 c67 = unpack2(acc[i][3]);
        float4 h0 = make_float4(c01.x, c01.y, c23.x, c23.y);
        float4 h1 = make_float4(c45.x, c45.y, c67.x, c67.y);

        float s = h0.x * s0.x + h0.y * s0.y + h0.z * s0.z + h0.w * s0.w +
                  h1.x * s1.x + h1.y * s1.y + h1.z * s1.z + h1.w * s1.w;
        float d = h0.x * d0.x + h0.y * d0.y + h0.z * d0.z + h0.w * d0.w +
                  h1.x * d1.x + h1.y * d1.y + h1.z * d1.z + h1.w * d1.w;
        // reduce within the 8 lanes of this head
#pragma unroll
        for (int msk = 1; msk < 8; msk <<= 1) {
            s += __shfl_xor_sync(0xffffffffu, s, msk);
            d += __shfl_xor_sync(0xffffffffu, d, msk);
        }
        const int m = m0 + ty * 8 + i;
        if (m < Ntot) {
            float ee = __expf(lrelu(s + d, SLOPE_ATT));   // self-loop weight
            float* hp = g_h + (size_t)m * HC + cbase;
            float* op = g_o + (size_t)m * HC + cbase;
            ((float4*)hp)[0] = h0;
            ((float4*)hp)[1] = h1;
            ((float4*)op)[0] = make_float4(h0.x * ee, h0.y * ee, h0.z * ee, h0.w * ee);
            ((float4*)op)[1] = make_float4(h1.x * ee, h1.y * ee, h1.z * ee, h1.w * ee);
            if ((tx & 7) == 0) {
                g_asrc[m * NH + head] = s;
                g_adst[m * NH + head] = d;
                g_den [m * NH + head] = ee;
            }
        }
    }
}

// ---------------------------------------------------------------------------
// K2: edge aggregation — one warp per edge; fused denom + message scatter.
// No max-shift: logits are ~N(0,2); exp() cannot overflow fp32 here and
// softmax is shift-invariant.
// ---------------------------------------------------------------------------
__global__ void k_edge_agg(const int* __restrict__ ei, int E) {
    const int e    = (blockIdx.x * blockDim.x + threadIdx.x) >> 5;
    const int lane = threadIdx.x & 31;
    if (e >= E) return;
    const int s = __ldg(ei + e);
    const int d = __ldg(ei + E + e);
    const int head = lane >> 3;
    const int ch   = head * CH + (lane & 7) * 8;

    float av = g_asrc[s * NH + head] + g_adst[d * NH + head];
    float ee = __expf(lrelu(av, SLOPE_ATT));
    if ((lane & 7) == 0) atomicAdd(&g_den[d * NH + head], ee);

    const float4* hp = (const float4*)(g_h + (size_t)s * HC + ch);
    float4 h0 = hp[0], h1 = hp[1];
    float* op = g_o + (size_t)d * HC + ch;
    red_add_v4(op,     make_float4(h0.x * ee, h0.y * ee, h0.z * ee, h0.w * ee));
    red_add_v4(op + 4, make_float4(h1.x * ee, h1.y * ee, h1.z * ee, h1.w * ee));
}

// ---------------------------------------------------------------------------
// K3: zero pooled accumulators
// ---------------------------------------------------------------------------
__global__ void k_pool_zero(int G) {
    const int i = blockIdx.x * blockDim.x + threadIdx.x;
    if (i < G * HC) g_pool[i] = 0.0f;
    if (i < G) g_cnt[i] = 0.0f;
}

// ---------------------------------------------------------------------------
// K4: node finalize (normalize + bias + leaky) and global mean-pool scatter
// ---------------------------------------------------------------------------
__global__ void k_node_pool(const int* __restrict__ batch,
                            const float* __restrict__ bias, int Ntot) {
    const int n    = (blockIdx.x * blockDim.x + threadIdx.x) >> 5;
    const int lane = threadIdx.x & 31;
    if (n >= Ntot) return;
    const int head = lane >> 3;
    const int ch   = head * CH + (lane & 7) * 8;

    float den = g_den[n * NH + head];
    const float4* op = (const float4*)(g_o + (size_t)n * HC + ch);
    float4 o0 = op[0], o1 = op[1];
    const float4* bp = (const float4*)(bias + ch);
    float4 b0 = bp[0], b1 = bp[1];

    float inv = 1.0f / den;
    o0 = make_float4(lrelu(o0.x * inv + b0.x, SLOPE_ACT),
                     lrelu(o0.y * inv + b0.y, SLOPE_ACT),
                     lrelu(o0.z * inv + b0.z, SLOPE_ACT),
                     lrelu(o0.w * inv + b0.w, SLOPE_ACT));
    o1 = make_float4(lrelu(o1.x * inv + b1.x, SLOPE_ACT),
                     lrelu(o1.y * inv + b1.y, SLOPE_ACT),
                     lrelu(o1.z * inv + b1.z, SLOPE_ACT),
                     lrelu(o1.w * inv + b1.w, SLOPE_ACT));

    const int b = batch[n];
    float* pp = g_pool + (size_t)b * HC + ch;
    red_add_v4(pp,     o0);
    red_add_v4(pp + 4, o1);
    if (lane == 0) atomicAdd(&g_cnt[b], 1.0f);
}

// ---------------------------------------------------------------------------
// K5: final GEMM  out[G,768] = (pool/cnt) @ fc1_w + fc1_b
// ---------------------------------------------------------------------------
__global__ void __launch_bounds__(256) k_final(const float* __restrict__ fw,
                                               const float* __restrict__ fb,
                                               float* __restrict__ out, int G) {
    __shared__ float p[16][HC];
    const int g0 = blockIdx.x * 16;
    const int j0 = blockIdx.y * 128;
    const int t  = threadIdx.x;

    for (int i = t; i < 16 * HC; i += 256) {
        const int g = i / HC, k = i % HC;
        float val = 0.0f;
        if (g0 + g < G) {
            float c = fmaxf(g_cnt[g0 + g], 1.0f);
            val = g_pool[(size_t)(g0 + g) * HC + k] / c;
        }
        p[g][k] = val;
    }
    __syncthreads();

    const int j  = j0 + (t & 127);
    const int gg = t >> 7;   // 0 or 1
    float acc[8];
#pragma unroll
    for (int r = 0; r < 8; r++) acc[r] = 0.0f;

    for (int k = 0; k < HC; k++) {
        float wv = fw[(size_t)k * NOUT + j];
#pragma unroll
        for (int r = 0; r < 8; r++) acc[r] += p[gg + r * 2][k] * wv;
    }
    float bv = fb[j];
#pragma unroll
    for (int r = 0; r < 8; r++) {
        const int g = g0 + gg + r * 2;
        if (g < G) out[(size_t)g * NOUT + j] = acc[r] + bv;
    }
}

// ---------------------------------------------------------------------------
// launch
// ---------------------------------------------------------------------------
extern "C" void kernel_launch(void* const* d_in, const int* in_sizes, int n_in,
                              void* d_out, int out_size) {
    const float* x       = (const float*)d_in[0];
    const int*   ei      = (const int*)d_in[1];
    const int*   batch   = (const int*)d_in[2];
    const float* lin_w   = (const float*)d_in[3];
    const float* att_src = (const float*)d_in[4];
    const float* att_dst = (const float*)d_in[5];
    const float* bias    = (const float*)d_in[6];
    const float* fc1_w   = (const float*)d_in[7];
    const float* fc1_b   = (const float*)d_in[8];
    float* out = (float*)d_out;

    const int N = in_sizes[0] / NIN;
    const int E = in_sizes[1] / 2;
    const int G = out_size / NOUT;

    k_pool_zero<<<(G * HC + 255) / 256, 256>>>(G);
    k_gemm_fused<<<(N + 63) / 64, 256>>>(x, lin_w, att_src, att_dst, N);
    k_edge_agg<<<(E + 7) / 8, 256>>>(ei, E);
    k_node_pool<<<(N + 7) / 8, 256>>>(batch, bias, N);
    dim3 fin_grid((G + 15) / 16, NOUT / 128);
    k_final<<<fin_grid, 256>>>(fc1_w, fc1_b, out, G);
}

// round 5
// speedup vs baseline: 1.2714x; 1.2714x over previous
#include <cuda_runtime.h>

// ---------------------------------------------------------------------------
// Problem constants
// ---------------------------------------------------------------------------
#define NH    4          // heads
#define CH    64         // channels per head
#define HC    256        // NH*CH
#define NIN   300
#define NOUT  768
#define MAXN  50048
#define MAXG  1024
#define SLOPE_ATT 0.2f
#define SLOPE_ACT 0.01f
#define RPB   64         // nodes per block in pooling kernel

// ---------------------------------------------------------------------------
// Scratch (device globals; no allocation allowed)
// ---------------------------------------------------------------------------
__device__ float g_h[MAXN * HC];       // node features after lin  [N, HC]
__device__ float g_o[MAXN * HC];       // weighted aggregation     [N, HC]
__device__ float g_asrc[MAXN * NH];
__device__ float g_adst[MAXN * NH];
__device__ float g_den[MAXN * NH];     // softmax denom (no max-shift needed)
__device__ float g_pool[MAXG * HC];
__device__ float g_cnt[MAXG];

// ---------------------------------------------------------------------------
// Helpers
// ---------------------------------------------------------------------------
__device__ __forceinline__ float lrelu(float v, float s) { return v > 0.0f ? v : s * v; }

__device__ __forceinline__ unsigned long long pack2(float lo, float hi) {
    unsigned long long r;
    asm("mov.b64 %0, {%1, %2};" : "=l"(r) : "f"(lo), "f"(hi));
    return r;
}
__device__ __forceinline__ float2 unpack2(unsigned long long v) {
    float2 f;
    asm("mov.b64 {%0, %1}, %2;" : "=f"(f.x), "=f"(f.y) : "l"(v));
    return f;
}
// packed dual-FMA: acc(2xf32) += a(2xf32) * b(2xf32)   (sm_100+)
__device__ __forceinline__ void ffma2(unsigned long long& acc,
                                      unsigned long long a, unsigned long long b) {
    asm("fma.rn.f32x2 %0, %1, %2, %0;" : "+l"(acc) : "l"(a), "l"(b));
}
__device__ __forceinline__ void red_add_v4(float* p, float4 v) {
    asm volatile("red.global.add.v4.f32 [%0], {%1, %2, %3, %4};"
                 :: "l"(p), "f"(v.x), "f"(v.y), "f"(v.z), "f"(v.w) : "memory");
}

// ---------------------------------------------------------------------------
// K1: h = x @ lin_w   (M=N nodes, K=300, Ncols=256)  — round-2 known-good
// 128x128 block tile, BK=8, 256 threads, 8x8 micro-tile with f32x2 FMAs
// ---------------------------------------------------------------------------
__global__ void __launch_bounds__(256) k_gemm_feat(const float* __restrict__ x,
                                                   const float* __restrict__ w,
                                                   int Ntot) {
    __shared__ float As[8][128];
    __shared__ float Bs[8][128];

    const int t  = threadIdx.x;
    const int m0 = blockIdx.x * 128;
    const int n0 = blockIdx.y * 128;
    const int tx = t & 15;           // 0..15 -> 8 cols each
    const int ty = t >> 4;           // 0..15 -> 8 rows each

    const int lm = t >> 1;           // row within tile
    const int lv = t & 1;            // k sub-quad
    const int kin = t >> 5;          // 0..7
    const int c4  = t & 31;          // 0..31 -> col = c4*4

    unsigned long long acc[8][4];
#pragma unroll
    for (int i = 0; i < 8; i++)
#pragma unroll
        for (int j = 0; j < 4; j++) acc[i][j] = 0ull;

    const int nk = (NIN + 7) / 8;    // 38

    float4 ra, rb;
    {
        const int k = lv * 4;
        const int m = m0 + lm;
        ra = make_float4(0.f, 0.f, 0.f, 0.f);
        if (m < Ntot) {
            if (k + 3 < NIN) ra = *(const float4*)(x + (size_t)m * NIN + k);
        }
        rb = make_float4(0.f, 0.f, 0.f, 0.f);
        if (kin < NIN) rb = *(const float4*)(w + (size_t)kin * HC + n0 + c4 * 4);
    }

    for (int kt = 0; kt < nk; kt++) {
        __syncthreads();
        As[lv * 4 + 0][lm] = ra.x;
        As[lv * 4 + 1][lm] = ra.y;
        As[lv * 4 + 2][lm] = ra.z;
        As[lv * 4 + 3][lm] = ra.w;
        ((float4*)&Bs[kin][0])[c4] = rb;
        __syncthreads();

        if (kt + 1 < nk) {
            const int k0 = (kt + 1) * 8;
            const int ka = k0 + lv * 4;
            const int m  = m0 + lm;
            ra = make_float4(0.f, 0.f, 0.f, 0.f);
            if (m < Ntot) {
                if (ka + 3 < NIN) {
                    ra = *(const float4*)(x + (size_t)m * NIN + ka);
                } else {
                    float* rv = &ra.x;
#pragma unroll
                    for (int j = 0; j < 4; j++)
                        if (ka + j < NIN) rv[j] = x[(size_t)m * NIN + ka + j];
                }
            }
            const int kb = k0 + kin;
            rb = make_float4(0.f, 0.f, 0.f, 0.f);
            if (kb < NIN) rb = *(const float4*)(w + (size_t)kb * HC + n0 + c4 * 4);
        }

#pragma unroll
        for (int k = 0; k < 8; k++) {
            float4 a0 = *(const float4*)&As[k][ty * 8];
            float4 a1 = *(const float4*)&As[k][ty * 8 + 4];
            float4 b0 = *(const float4*)&Bs[k][tx * 8];
            float4 b1 = *(const float4*)&Bs[k][tx * 8 + 4];
            unsigned long long bp[4] = {pack2(b0.x, b0.y), pack2(b0.z, b0.w),
                                        pack2(b1.x, b1.y), pack2(b1.z, b1.w)};
            float am[8] = {a0.x, a0.y, a0.z, a0.w, a1.x, a1.y, a1.z, a1.w};
#pragma unroll
            for (int i = 0; i < 8; i++) {
                unsigned long long ap = pack2(am[i], am[i]);
#pragma unroll
                for (int j = 0; j < 4; j++) ffma2(acc[i][j], ap, bp[j]);
            }
        }
    }

#pragma unroll
    for (int i = 0; i < 8; i++) {
        const int m = m0 + ty * 8 + i;
        if (m >= Ntot) continue;
        float* dst = g_h + (size_t)m * HC + n0 + tx * 8;
        float2 c01 = unpack2(acc[i][0]);
        float2 c23 = unpack2(acc[i][1]);
        float2 c45 = unpack2(acc[i][2]);
        float2 c67 = unpack2(acc[i][3]);
        ((float4*)dst)[0] = make_float4(c01.x, c01.y, c23.x, c23.y);
        ((float4*)dst)[1] = make_float4(c45.x, c45.y, c67.x, c67.y);
    }
}

// ---------------------------------------------------------------------------
// K2: merged node attention + self-loop init.
// One warp per node. Computes a_src/a_dst per head (8-lane dot reductions),
// ee = exp(lrelu(s+d)) (no max-shift), writes g_asrc/g_adst/g_den and
// g_o = h * ee — all from a single read of g_h.
// ---------------------------------------------------------------------------
__global__ void k_node_att_init(const float* __restrict__ att_src,
                                const float* __restrict__ att_dst, int Ntot) {
    const int n    = (blockIdx.x * blockDim.x + threadIdx.x) >> 5;
    const int lane = threadIdx.x & 31;
    if (n >= Ntot) return;
    const int head = lane >> 3;
    const int ch   = head * CH + (lane & 7) * 8;

    const float4* hp = (const float4*)(g_h + (size_t)n * HC + ch);
    float4 h0 = hp[0], h1 = hp[1];
    const float4* sp = (const float4*)(att_src + ch);
    const float4* dp = (const float4*)(att_dst + ch);
    float4 s0 = sp[0], s1 = sp[1];
    float4 d0 = dp[0], d1 = dp[1];

    float s = h0.x * s0.x + h0.y * s0.y + h0.z * s0.z + h0.w * s0.w +
              h1.x * s1.x + h1.y * s1.y + h1.z * s1.z + h1.w * s1.w;
    float d = h0.x * d0.x + h0.y * d0.y + h0.z * d0.z + h0.w * d0.w +
              h1.x * d1.x + h1.y * d1.y + h1.z * d1.z + h1.w * d1.w;
#pragma unroll
    for (int m = 1; m < 8; m <<= 1) {
        s += __shfl_xor_sync(0xffffffffu, s, m);
        d += __shfl_xor_sync(0xffffffffu, d, m);
    }
    float ee = __expf(lrelu(s + d, SLOPE_ATT));   // self-loop weight

    float4* op = (float4*)(g_o + (size_t)n * HC + ch);
    op[0] = make_float4(h0.x * ee, h0.y * ee, h0.z * ee, h0.w * ee);
    op[1] = make_float4(h1.x * ee, h1.y * ee, h1.z * ee, h1.w * ee);

    if ((lane & 7) == 0) {
        g_asrc[n * NH + head] = s;
        g_adst[n * NH + head] = d;
        g_den [n * NH + head] = ee;
    }
}

// ---------------------------------------------------------------------------
// K3: edge aggregation — one warp per edge; fused denom + message scatter.
// No max-shift: logits ~N(0,2); exp cannot overflow fp32; softmax is
// shift-invariant.
// ---------------------------------------------------------------------------
__global__ void k_edge_agg(const int* __restrict__ ei, int E) {
    const int e    = (blockIdx.x * blockDim.x + threadIdx.x) >> 5;
    const int lane = threadIdx.x & 31;
    if (e >= E) return;
    const int s = __ldg(ei + e);
    const int d = __ldg(ei + E + e);
    const int head = lane >> 3;
    const int ch   = head * CH + (lane & 7) * 8;

    float av = g_asrc[s * NH + head] + g_adst[d * NH + head];
    float ee = __expf(lrelu(av, SLOPE_ATT));
    if ((lane & 7) == 0) atomicAdd(&g_den[d * NH + head], ee);

    const float4* hp = (const float4*)(g_h + (size_t)s * HC + ch);
    float4 h0 = hp[0], h1 = hp[1];
    float* op = g_o + (size_t)d * HC + ch;
    red_add_v4(op,     make_float4(h0.x * ee, h0.y * ee, h0.z * ee, h0.w * ee));
    red_add_v4(op + 4, make_float4(h1.x * ee, h1.y * ee, h1.z * ee, h1.w * ee));
}

// ---------------------------------------------------------------------------
// K4: zero pooled accumulators
// ---------------------------------------------------------------------------
__global__ void k_pool_zero(int G) {
    const int i = blockIdx.x * blockDim.x + threadIdx.x;
    if (i < G * HC) g_pool[i] = 0.0f;
    if (i < G) g_cnt[i] = 0.0f;
}

// ---------------------------------------------------------------------------
// K5: node finalize + segmented mean-pool.
// batch is SORTED. Block owns RPB consecutive nodes; thread = channel.
// Run-length accumulate per graph segment in a register; flush one atomic
// row per segment boundary (atomics: 3.2M -> ~260k). Depth-2 prefetch on
// the g_o row stream; per-node 1/den precomputed in smem.
// ---------------------------------------------------------------------------
__global__ void __launch_bounds__(256) k_node_pool(const int* __restrict__ batch,
                                                   const float* __restrict__ bias,
                                                   int Ntot) {
    __shared__ int   sb[RPB];
    __shared__ float sinv[RPB * NH];

    const int n0 = blockIdx.x * RPB;
    if (n0 >= Ntot) return;
    const int t = threadIdx.x;
    const int cnt_local = min(RPB, Ntot - n0);

    if (t < cnt_local) sb[t] = batch[n0 + t];
    if (t < cnt_local * NH) {
        const int i = t >> 2, h = t & 3;
        sinv[t] = 1.0f / g_den[(n0 + i) * NH + h];
    }
    __syncthreads();

    const float bv   = bias[t];
    const int   head = t >> 6;

    float acc = 0.0f;
    int   cur = sb[0];
    int   run = 0;

    float cv = g_o[(size_t)n0 * HC + t];   // prefetched current row value
    for (int i = 0; i < cnt_local; i++) {
        float nv = 0.0f;
        if (i + 1 < cnt_local)
            nv = g_o[(size_t)(n0 + i + 1) * HC + t];   // issue next load early

        const int bn = sb[i];
        if (bn != cur) {
            atomicAdd(&g_pool[(size_t)cur * HC + t], acc);
            if (t == 0) atomicAdd(&g_cnt[cur], (float)run);
            acc = 0.0f; run = 0; cur = bn;
        }
        acc += lrelu(cv * sinv[i * NH + head] + bv, SLOPE_ACT);
        run++;
        cv = nv;
    }
    atomicAdd(&g_pool[(size_t)cur * HC + t], acc);
    if (t == 0) atomicAdd(&g_cnt[cur], (float)run);
}

// ---------------------------------------------------------------------------
// K6: final GEMM  out[G,768] = (pool/cnt) @ fc1_w + fc1_b
// ---------------------------------------------------------------------------
__global__ void __launch_bounds__(256) k_final(const float* __restrict__ fw,
                                               const float* __restrict__ fb,
                                               float* __restrict__ out, int G) {
    __shared__ float p[16][HC];
    const int g0 = blockIdx.x * 16;
    const int j0 = blockIdx.y * 128;
    const int t  = threadIdx.x;

    for (int i = t; i < 16 * HC; i += 256) {
        const int g = i / HC, k = i % HC;
        float val = 0.0f;
        if (g0 + g < G) {
            float c = fmaxf(g_cnt[g0 + g], 1.0f);
            val = g_pool[(size_t)(g0 + g) * HC + k] / c;
        }
        p[g][k] = val;
    }
    __syncthreads();

    const int j  = j0 + (t & 127);
    const int gg = t >> 7;   // 0 or 1
    float acc[8];
#pragma unroll
    for (int r = 0; r < 8; r++) acc[r] = 0.0f;

    for (int k = 0; k < HC; k++) {
        float wv = fw[(size_t)k * NOUT + j];
#pragma unroll
        for (int r = 0; r < 8; r++) acc[r] += p[gg + r * 2][k] * wv;
    }
    float bv = fb[j];
#pragma unroll
    for (int r = 0; r < 8; r++) {
        const int g = g0 + gg + r * 2;
        if (g < G) out[(size_t)g * NOUT + j] = acc[r] + bv;
    }
}

// ---------------------------------------------------------------------------
// launch
// ---------------------------------------------------------------------------
extern "C" void kernel_launch(void* const* d_in, const int* in_sizes, int n_in,
                              void* d_out, int out_size) {
    const float* x       = (const float*)d_in[0];
    const int*   ei      = (const int*)d_in[1];
    const int*   batch   = (const int*)d_in[2];
    const float* lin_w   = (const float*)d_in[3];
    const float* att_src = (const float*)d_in[4];
    const float* att_dst = (const float*)d_in[5];
    const float* bias    = (const float*)d_in[6];
    const float* fc1_w   = (const float*)d_in[7];
    const float* fc1_b   = (const float*)d_in[8];
    float* out = (float*)d_out;

    const int N = in_sizes[0] / NIN;
    const int E = in_sizes[1] / 2;
    const int G = out_size / NOUT;

    k_pool_zero<<<(G * HC + 255) / 256, 256>>>(G);
    dim3 gemm_grid((N + 127) / 128, HC / 128);
    k_gemm_feat<<<gemm_grid, 256>>>(x, lin_w, N);
    k_node_att_init<<<(N + 7) / 8, 256>>>(att_src, att_dst, N);
    k_edge_agg<<<(E + 7) / 8, 256>>>(ei, E);
    k_node_pool<<<(N + RPB - 1) / RPB, 256>>>(batch, bias, N);
    dim3 fin_grid((G + 15) / 16, NOUT / 128);
    k_final<<<fin_grid, 256>>>(fc1_w, fc1_b, out, G);
}

// round 7
// speedup vs baseline: 1.4944x; 1.1754x over previous
#include <cuda_runtime.h>

// ---------------------------------------------------------------------------
// Problem constants
// ---------------------------------------------------------------------------
#define NH    4          // heads
#define CH    64         // channels per head
#define HC    256        // NH*CH
#define NIN   300
#define NOUT  768
#define MAXN  50048
#define MAXG  1024
#define SLOPE_ATT 0.2f
#define SLOPE_ACT 0.01f
#define RPB   64         // nodes per block in pooling kernel

// ---------------------------------------------------------------------------
// Scratch (device globals; no allocation allowed)
// ---------------------------------------------------------------------------
__device__ float g_h[MAXN * HC];       // node features after lin  [N, HC]
__device__ float g_o[MAXN * HC];       // weighted aggregation     [N, HC]
__device__ float g_asrc[MAXN * NH];
__device__ float g_adst[MAXN * NH];
__device__ float g_den[MAXN * NH];     // softmax denom (no max-shift needed)
__device__ float g_pool[MAXG * HC];
__device__ float g_cnt[MAXG];

// ---------------------------------------------------------------------------
// Helpers
// ---------------------------------------------------------------------------
__device__ __forceinline__ float lrelu(float v, float s) { return v > 0.0f ? v : s * v; }

__device__ __forceinline__ unsigned long long pack2(float lo, float hi) {
    unsigned long long r;
    asm("mov.b64 %0, {%1, %2};" : "=l"(r) : "f"(lo), "f"(hi));
    return r;
}
__device__ __forceinline__ float2 unpack2(unsigned long long v) {
    float2 f;
    asm("mov.b64 {%0, %1}, %2;" : "=f"(f.x), "=f"(f.y) : "l"(v));
    return f;
}
// packed dual-FMA: acc(2xf32) += a(2xf32) * b(2xf32)   (sm_100+)
__device__ __forceinline__ void ffma2(unsigned long long& acc,
                                      unsigned long long a, unsigned long long b) {
    asm("fma.rn.f32x2 %0, %1, %2, %0;" : "+l"(acc) : "l"(a), "l"(b));
}
__device__ __forceinline__ void red_add_v4(float* p, float4 v) {
    asm volatile("red.global.add.v4.f32 [%0], {%1, %2, %3, %4};"
                 :: "l"(p), "f"(v.x), "f"(v.y), "f"(v.z), "f"(v.w) : "memory");
}

// ---------------------------------------------------------------------------
// K1: h = x @ lin_w   (M=N nodes, K=300, Ncols=256)  — known-good
// 128x128 block tile, BK=8, 256 threads, 8x8 micro-tile with f32x2 FMAs
// ---------------------------------------------------------------------------
__global__ void __launch_bounds__(256) k_gemm_feat(const float* __restrict__ x,
                                                   const float* __restrict__ w,
                                                   int Ntot) {
    __shared__ float As[8][128];
    __shared__ float Bs[8][128];

    const int t  = threadIdx.x;
    const int m0 = blockIdx.x * 128;
    const int n0 = blockIdx.y * 128;
    const int tx = t & 15;           // 0..15 -> 8 cols each
    const int ty = t >> 4;           // 0..15 -> 8 rows each

    const int lm = t >> 1;           // row within tile
    const int lv = t & 1;            // k sub-quad
    const int kin = t >> 5;          // 0..7
    const int c4  = t & 31;          // 0..31 -> col = c4*4

    unsigned long long acc[8][4];
#pragma unroll
    for (int i = 0; i < 8; i++)
#pragma unroll
        for (int j = 0; j < 4; j++) acc[i][j] = 0ull;

    const int nk = (NIN + 7) / 8;    // 38

    float4 ra, rb;
    {
        const int k = lv * 4;
        const int m = m0 + lm;
        ra = make_float4(0.f, 0.f, 0.f, 0.f);
        if (m < Ntot) {
            if (k + 3 < NIN) ra = *(const float4*)(x + (size_t)m * NIN + k);
        }
        rb = make_float4(0.f, 0.f, 0.f, 0.f);
        if (kin < NIN) rb = *(const float4*)(w + (size_t)kin * HC + n0 + c4 * 4);
    }

    for (int kt = 0; kt < nk; kt++) {
        __syncthreads();
        As[lv * 4 + 0][lm] = ra.x;
        As[lv * 4 + 1][lm] = ra.y;
        As[lv * 4 + 2][lm] = ra.z;
        As[lv * 4 + 3][lm] = ra.w;
        ((float4*)&Bs[kin][0])[c4] = rb;
        __syncthreads();

        if (kt + 1 < nk) {
            const int k0 = (kt + 1) * 8;
            const int ka = k0 + lv * 4;
            const int m  = m0 + lm;
            ra = make_float4(0.f, 0.f, 0.f, 0.f);
            if (m < Ntot) {
                if (ka + 3 < NIN) {
                    ra = *(const float4*)(x + (size_t)m * NIN + ka);
                } else {
                    float* rv = &ra.x;
#pragma unroll
                    for (int j = 0; j < 4; j++)
                        if (ka + j < NIN) rv[j] = x[(size_t)m * NIN + ka + j];
                }
            }
            const int kb = k0 + kin;
            rb = make_float4(0.f, 0.f, 0.f, 0.f);
            if (kb < NIN) rb = *(const float4*)(w + (size_t)kb * HC + n0 + c4 * 4);
        }

#pragma unroll
        for (int k = 0; k < 8; k++) {
            float4 a0 = *(const float4*)&As[k][ty * 8];
            float4 a1 = *(const float4*)&As[k][ty * 8 + 4];
            float4 b0 = *(const float4*)&Bs[k][tx * 8];
            float4 b1 = *(const float4*)&Bs[k][tx * 8 + 4];
            unsigned long long bp[4] = {pack2(b0.x, b0.y), pack2(b0.z, b0.w),
                                        pack2(b1.x, b1.y), pack2(b1.z, b1.w)};
            float am[8] = {a0.x, a0.y, a0.z, a0.w, a1.x, a1.y, a1.z, a1.w};
#pragma unroll
            for (int i = 0; i < 8; i++) {
                unsigned long long ap = pack2(am[i], am[i]);
#pragma unroll
                for (int j = 0; j < 4; j++) ffma2(acc[i][j], ap, bp[j]);
            }
        }
    }

#pragma unroll
    for (int i = 0; i < 8; i++) {
        const int m = m0 + ty * 8 + i;
        if (m >= Ntot) continue;
        float* dst = g_h + (size_t)m * HC + n0 + tx * 8;
        float2 c01 = unpack2(acc[i][0]);
        float2 c23 = unpack2(acc[i][1]);
        float2 c45 = unpack2(acc[i][2]);
        float2 c67 = unpack2(acc[i][3]);
        ((float4*)dst)[0] = make_float4(c01.x, c01.y, c23.x, c23.y);
        ((float4*)dst)[1] = make_float4(c45.x, c45.y, c67.x, c67.y);
    }
}

// ---------------------------------------------------------------------------
// K2: merged node attention + self-loop init.  (one warp per node)
// ---------------------------------------------------------------------------
__global__ void k_node_att_init(const float* __restrict__ att_src,
                                const float* __restrict__ att_dst, int Ntot) {
    const int n    = (blockIdx.x * blockDim.x + threadIdx.x) >> 5;
    const int lane = threadIdx.x & 31;
    if (n >= Ntot) return;
    const int head = lane >> 3;
    const int ch   = head * CH + (lane & 7) * 8;

    const float4* hp = (const float4*)(g_h + (size_t)n * HC + ch);
    float4 h0 = hp[0], h1 = hp[1];
    const float4* sp = (const float4*)(att_src + ch);
    const float4* dp = (const float4*)(att_dst + ch);
    float4 s0 = sp[0], s1 = sp[1];
    float4 d0 = dp[0], d1 = dp[1];

    float s = h0.x * s0.x + h0.y * s0.y + h0.z * s0.z + h0.w * s0.w +
              h1.x * s1.x + h1.y * s1.y + h1.z * s1.z + h1.w * s1.w;
    float d = h0.x * d0.x + h0.y * d0.y + h0.z * d0.z + h0.w * d0.w +
              h1.x * d1.x + h1.y * d1.y + h1.z * d1.z + h1.w * d1.w;
#pragma unroll
    for (int m = 1; m < 8; m <<= 1) {
        s += __shfl_xor_sync(0xffffffffu, s, m);
        d += __shfl_xor_sync(0xffffffffu, d, m);
    }
    float ee = __expf(lrelu(s + d, SLOPE_ATT));   // self-loop weight

    float4* op = (float4*)(g_o + (size_t)n * HC + ch);
    op[0] = make_float4(h0.x * ee, h0.y * ee, h0.z * ee, h0.w * ee);
    op[1] = make_float4(h1.x * ee, h1.y * ee, h1.z * ee, h1.w * ee);

    if ((lane & 7) == 0) {
        g_asrc[n * NH + head] = s;
        g_adst[n * NH + head] = d;
        g_den [n * NH + head] = ee;
    }
}

// ---------------------------------------------------------------------------
// K3: edge aggregation — one warp per edge, CONTIGUOUS lane mapping.
// Lane l owns channels [l*4, l*4+4) (heads 0/1 half) and [128+l*4, ...)
// (heads 2/3 half): every LDG.128 / RED.128 covers 512 contiguous bytes
// = 4 cache lines per wavefront instead of 8 -> halves L1tex wavefronts.
// ---------------------------------------------------------------------------
__global__ void k_edge_agg(const int* __restrict__ ei, int E) {
    const int e    = (blockIdx.x * blockDim.x + threadIdx.x) >> 5;
    const int lane = threadIdx.x & 31;
    if (e >= E) return;
    const int s = __ldg(ei + e);
    const int d = __ldg(ei + E + e);

    const int hlo = lane >> 4;        // head of low half-row  (0 or 1)
    const int hhi = hlo + 2;          // head of high half-row (2 or 3)

    const float* as = g_asrc + s * NH;
    const float* ad = g_adst + d * NH;
    float e0 = __expf(lrelu(as[hlo] + ad[hlo], SLOPE_ATT));
    float e1 = __expf(lrelu(as[hhi] + ad[hhi], SLOPE_ATT));

    // lanes 0 and 16 each own 2 of the 4 per-head denom atomics
    if ((lane & 15) == 0) {
        float* dn = g_den + d * NH;
        atomicAdd(dn + hlo, e0);
        atomicAdd(dn + hhi, e1);
    }

    const float* hp = g_h + (size_t)s * HC + lane * 4;
    float4 v0 = *(const float4*)(hp);          // cols [lane*4, +4)
    float4 v1 = *(const float4*)(hp + 128);    // cols [128+lane*4, +4)

    float* op = g_o + (size_t)d * HC + lane * 4;
    red_add_v4(op,       make_float4(v0.x * e0, v0.y * e0, v0.z * e0, v0.w * e0));
    red_add_v4(op + 128, make_float4(v1.x * e1, v1.y * e1, v1.z * e1, v1.w * e1));
}

// ---------------------------------------------------------------------------
// K4: zero pooled accumulators
// ---------------------------------------------------------------------------
__global__ void k_pool_zero(int G) {
    const int i = blockIdx.x * blockDim.x + threadIdx.x;
    if (i < G * HC) g_pool[i] = 0.0f;
    if (i < G) g_cnt[i] = 0.0f;
}

// ---------------------------------------------------------------------------
// K5: node finalize + segmented mean-pool (batch sorted; run-length flush)
// ---------------------------------------------------------------------------
__global__ void __launch_bounds__(256) k_node_pool(const int* __restrict__ batch,
                                                   const float* __restrict__ bias,
                                                   int Ntot) {
    __shared__ int   sb[RPB];
    __shared__ float sinv[RPB * NH];

    const int n0 = blockIdx.x * RPB;
    if (n0 >= Ntot) return;
    const int t = threadIdx.x;
    const int cnt_local = min(RPB, Ntot - n0);

    if (t < cnt_local) sb[t] = batch[n0 + t];
    if (t < cnt_local * NH) {
        const int i = t >> 2, h = t & 3;
        sinv[t] = 1.0f / g_den[(n0 + i) * NH + h];
    }
    __syncthreads();

    const float bv   = bias[t];
    const int   head = t >> 6;

    float acc = 0.0f;
    int   cur = sb[0];
    int   run = 0;

    float cv = g_o[(size_t)n0 * HC + t];
    for (int i = 0; i < cnt_local; i++) {
        float nv = 0.0f;
        if (i + 1 < cnt_local)
            nv = g_o[(size_t)(n0 + i + 1) * HC + t];

        const int bn = sb[i];
        if (bn != cur) {
            atomicAdd(&g_pool[(size_t)cur * HC + t], acc);
            if (t == 0) atomicAdd(&g_cnt[cur], (float)run);
            acc = 0.0f; run = 0; cur = bn;
        }
        acc += lrelu(cv * sinv[i * NH + head] + bv, SLOPE_ACT);
        run++;
        cv = nv;
    }
    atomicAdd(&g_pool[(size_t)cur * HC + t], acc);
    if (t == 0) atomicAdd(&g_cnt[cur], (float)run);
}

// ---------------------------------------------------------------------------
// K6: final GEMM  out[G,768] = (pool/cnt) @ fc1_w + fc1_b
// ---------------------------------------------------------------------------
__global__ void __launch_bounds__(256) k_final(const float* __restrict__ fw,
                                               const float* __restrict__ fb,
                                               float* __restrict__ out, int G) {
    __shared__ float p[16][HC];
    const int g0 = blockIdx.x * 16;
    const int j0 = blockIdx.y * 128;
    const int t  = threadIdx.x;

    for (int i = t; i < 16 * HC; i += 256) {
        const int g = i / HC, k = i % HC;
        float val = 0.0f;
        if (g0 + g < G) {
            float c = fmaxf(g_cnt[g0 + g], 1.0f);
            val = g_pool[(size_t)(g0 + g) * HC + k] / c;
        }
        p[g][k] = val;
    }
    __syncthreads();

    const int j  = j0 + (t & 127);
    const int gg = t >> 7;   // 0 or 1
    float acc[8];
#pragma unroll
    for (int r = 0; r < 8; r++) acc[r] = 0.0f;

    for (int k = 0; k < HC; k++) {
        float wv = fw[(size_t)k * NOUT + j];
#pragma unroll
        for (int r = 0; r < 8; r++) acc[r] += p[gg + r * 2][k] * wv;
    }
    float bv = fb[j];
#pragma unroll
    for (int r = 0; r < 8; r++) {
        const int g = g0 + gg + r * 2;
        if (g < G) out[(size_t)g * NOUT + j] = acc[r] + bv;
    }
}

// ---------------------------------------------------------------------------
// launch
// ---------------------------------------------------------------------------
extern "C" void kernel_launch(void* const* d_in, const int* in_sizes, int n_in,
                              void* d_out, int out_size) {
    const float* x       = (const float*)d_in[0];
    const int*   ei      = (const int*)d_in[1];
    const int*   batch   = (const int*)d_in[2];
    const float* lin_w   = (const float*)d_in[3];
    const float* att_src = (const float*)d_in[4];
    const float* att_dst = (const float*)d_in[5];
    const float* bias    = (const float*)d_in[6];
    const float* fc1_w   = (const float*)d_in[7];
    const float* fc1_b   = (const float*)d_in[8];
    float* out = (float*)d_out;

    const int N = in_sizes[0] / NIN;
    const int E = in_sizes[1] / 2;
    const int G = out_size / NOUT;

    k_pool_zero<<<(G * HC + 255) / 256, 256>>>(G);
    dim3 gemm_grid((N + 127) / 128, HC / 128);
    k_gemm_feat<<<gemm_grid, 256>>>(x, lin_w, N);
    k_node_att_init<<<(N + 7) / 8, 256>>>(att_src, att_dst, N);
    k_edge_agg<<<(E + 7) / 8, 256>>>(ei, E);
    k_node_pool<<<(N + RPB - 1) / RPB, 256>>>(batch, bias, N);
    dim3 fin_grid((G + 15) / 16, NOUT / 128);
    k_final<<<fin_grid, 256>>>(fc1_w, fc1_b, out, G);
}

// round 8
// speedup vs baseline: 1.7073x; 1.1424x over previous
#include <cuda_runtime.h>

// ---------------------------------------------------------------------------
// Problem constants
// ---------------------------------------------------------------------------
#define NH    4          // heads
#define CH    64         // channels per head
#define HC    256        // NH*CH
#define NIN   300
#define NOUT  768
#define MAXN  50048
#define MAXE  800000
#define MAXG  1024
#define SLOPE_ATT 0.2f
#define SLOPE_ACT 0.01f
#define RPB   64         // nodes per block in pooling kernel
#define SCB   512        // scan block size

// ---------------------------------------------------------------------------
// Scratch (device globals; no allocation allowed)
// ---------------------------------------------------------------------------
__device__ float  g_h[MAXN * HC];      // node features after lin  [N, HC]
__device__ float  g_o[MAXN * HC];      // finalized node output    [N, HC]
__device__ float  g_asrc[MAXN * NH];
__device__ float  g_adst[MAXN * NH];
__device__ int    g_cntn[MAXN];        // per-destination edge counts
__device__ int    g_off[MAXN + 1];     // CSR offsets
__device__ int    g_offt[MAXN];        // per-block-scan temp
__device__ int    g_pos[MAXN];         // running slot counters
__device__ int    g_bsum[128];
__device__ int    g_boff[128];
__device__ int    g_esrc[MAXE];        // CSR: source node per slot
__device__ float4 g_ew[MAXE];          // CSR: per-head weights per slot
__device__ float  g_pool[MAXG * HC];
__device__ float  g_cnt[MAXG];

// ---------------------------------------------------------------------------
// Helpers
// ---------------------------------------------------------------------------
__device__ __forceinline__ float lrelu(float v, float s) { return v > 0.0f ? v : s * v; }

__device__ __forceinline__ unsigned long long pack2(float lo, float hi) {
    unsigned long long r;
    asm("mov.b64 %0, {%1, %2};" : "=l"(r) : "f"(lo), "f"(hi));
    return r;
}
__device__ __forceinline__ float2 unpack2(unsigned long long v) {
    float2 f;
    asm("mov.b64 {%0, %1}, %2;" : "=f"(f.x), "=f"(f.y) : "l"(v));
    return f;
}
__device__ __forceinline__ void ffma2(unsigned long long& acc,
                                      unsigned long long a, unsigned long long b) {
    asm("fma.rn.f32x2 %0, %1, %2, %0;" : "+l"(acc) : "l"(a), "l"(b));
}

// ---------------------------------------------------------------------------
// K1: h = x @ lin_w — known-good 128x128 tile, BK=8, f32x2 FMAs
// ---------------------------------------------------------------------------
__global__ void __launch_bounds__(256) k_gemm_feat(const float* __restrict__ x,
                                                   const float* __restrict__ w,
                                                   int Ntot) {
    __shared__ float As[8][128];
    __shared__ float Bs[8][128];

    const int t  = threadIdx.x;
    const int m0 = blockIdx.x * 128;
    const int n0 = blockIdx.y * 128;
    const int tx = t & 15;
    const int ty = t >> 4;

    const int lm = t >> 1;
    const int lv = t & 1;
    const int kin = t >> 5;
    const int c4  = t & 31;

    unsigned long long acc[8][4];
#pragma unroll
    for (int i = 0; i < 8; i++)
#pragma unroll
        for (int j = 0; j < 4; j++) acc[i][j] = 0ull;

    const int nk = (NIN + 7) / 8;    // 38

    float4 ra, rb;
    {
        const int k = lv * 4;
        const int m = m0 + lm;
        ra = make_float4(0.f, 0.f, 0.f, 0.f);
        if (m < Ntot) {
            if (k + 3 < NIN) ra = *(const float4*)(x + (size_t)m * NIN + k);
        }
        rb = make_float4(0.f, 0.f, 0.f, 0.f);
        if (kin < NIN) rb = *(const float4*)(w + (size_t)kin * HC + n0 + c4 * 4);
    }

    for (int kt = 0; kt < nk; kt++) {
        __syncthreads();
        As[lv * 4 + 0][lm] = ra.x;
        As[lv * 4 + 1][lm] = ra.y;
        As[lv * 4 + 2][lm] = ra.z;
        As[lv * 4 + 3][lm] = ra.w;
        ((float4*)&Bs[kin][0])[c4] = rb;
        __syncthreads();

        if (kt + 1 < nk) {
            const int k0 = (kt + 1) * 8;
            const int ka = k0 + lv * 4;
            const int m  = m0 + lm;
            ra = make_float4(0.f, 0.f, 0.f, 0.f);
            if (m < Ntot) {
                if (ka + 3 < NIN) {
                    ra = *(const float4*)(x + (size_t)m * NIN + ka);
                } else {
                    float* rv = &ra.x;
#pragma unroll
                    for (int j = 0; j < 4; j++)
                        if (ka + j < NIN) rv[j] = x[(size_t)m * NIN + ka + j];
                }
            }
            const int kb = k0 + kin;
            rb = make_float4(0.f, 0.f, 0.f, 0.f);
            if (kb < NIN) rb = *(const float4*)(w + (size_t)kb * HC + n0 + c4 * 4);
        }

#pragma unroll
        for (int k = 0; k < 8; k++) {
            float4 a0 = *(const float4*)&As[k][ty * 8];
            float4 a1 = *(const float4*)&As[k][ty * 8 + 4];
            float4 b0 = *(const float4*)&Bs[k][tx * 8];
            float4 b1 = *(const float4*)&Bs[k][tx * 8 + 4];
            unsigned long long bp[4] = {pack2(b0.x, b0.y), pack2(b0.z, b0.w),
                                        pack2(b1.x, b1.y), pack2(b1.z, b1.w)};
            float am[8] = {a0.x, a0.y, a0.z, a0.w, a1.x, a1.y, a1.z, a1.w};
#pragma unroll
            for (int i = 0; i < 8; i++) {
                unsigned long long ap = pack2(am[i], am[i]);
#pragma unroll
                for (int j = 0; j < 4; j++) ffma2(acc[i][j], ap, bp[j]);
            }
        }
    }

#pragma unroll
    for (int i = 0; i < 8; i++) {
        const int m = m0 + ty * 8 + i;
        if (m >= Ntot) continue;
        float* dst = g_h + (size_t)m * HC + n0 + tx * 8;
        float2 c01 = unpack2(acc[i][0]);
        float2 c23 = unpack2(acc[i][1]);
        float2 c45 = unpack2(acc[i][2]);
        float2 c67 = unpack2(acc[i][3]);
        ((float4*)dst)[0] = make_float4(c01.x, c01.y, c23.x, c23.y);
        ((float4*)dst)[1] = make_float4(c45.x, c45.y, c67.x, c67.y);
    }
}

// ---------------------------------------------------------------------------
// K2: node attention logits (read-only pass over g_h) — one warp per node
// ---------------------------------------------------------------------------
__global__ void k_node_att(const float* __restrict__ att_src,
                           const float* __restrict__ att_dst, int Ntot) {
    const int n    = (blockIdx.x * blockDim.x + threadIdx.x) >> 5;
    const int lane = threadIdx.x & 31;
    if (n >= Ntot) return;
    const int head = lane >> 3;
    const int ch   = head * CH + (lane & 7) * 8;

    const float4* hp = (const float4*)(g_h + (size_t)n * HC + ch);
    float4 h0 = hp[0], h1 = hp[1];
    const float4* sp = (const float4*)(att_src + ch);
    const float4* dp = (const float4*)(att_dst + ch);
    float4 s0 = sp[0], s1 = sp[1];
    float4 d0 = dp[0], d1 = dp[1];

    float s = h0.x * s0.x + h0.y * s0.y + h0.z * s0.z + h0.w * s0.w +
              h1.x * s1.x + h1.y * s1.y + h1.z * s1.z + h1.w * s1.w;
    float d = h0.x * d0.x + h0.y * d0.y + h0.z * d0.z + h0.w * d0.w +
              h1.x * d1.x + h1.y * d1.y + h1.z * d1.z + h1.w * d1.w;
#pragma unroll
    for (int m = 1; m < 8; m <<= 1) {
        s += __shfl_xor_sync(0xffffffffu, s, m);
        d += __shfl_xor_sync(0xffffffffu, d, m);
    }
    if ((lane & 7) == 0) {
        g_asrc[n * NH + head] = s;
        g_adst[n * NH + head] = d;
    }
}

// ---------------------------------------------------------------------------
// K0: zero accumulators (pool, counts, per-dst counters)
// ---------------------------------------------------------------------------
__global__ void k_zero(int Gtot, int Ntot) {
    const int i = blockIdx.x * blockDim.x + threadIdx.x;
    if (i < Gtot * HC) g_pool[i] = 0.0f;
    if (i < Gtot) g_cnt[i] = 0.0f;
    if (i < Ntot) g_cntn[i] = 0;
}

// ---------------------------------------------------------------------------
// CSR build: count -> scan(3) -> scatter
// ---------------------------------------------------------------------------
__global__ void k_count(const int* __restrict__ ei, int E) {
    const int e = blockIdx.x * blockDim.x + threadIdx.x;
    if (e < E) atomicAdd(&g_cntn[ei[E + e]], 1);
}

__global__ void __launch_bounds__(SCB) k_scan1(int Ntot) {
    __shared__ int sm[SCB];
    const int t = threadIdx.x;
    const int i = blockIdx.x * SCB + t;
    int v = (i < Ntot) ? g_cntn[i] : 0;
    sm[t] = v;
    __syncthreads();
#pragma unroll
    for (int o = 1; o < SCB; o <<= 1) {
        int x = (t >= o) ? sm[t - o] : 0;
        __syncthreads();
        sm[t] += x;
        __syncthreads();
    }
    if (i < Ntot) g_offt[i] = sm[t] - v;        // exclusive within block
    if (t == SCB - 1) g_bsum[blockIdx.x] = sm[t];
}

__global__ void __launch_bounds__(128) k_scan2(int nb, int Ntot) {
    __shared__ int sm[128];
    const int t = threadIdx.x;
    int v = (t < nb) ? g_bsum[t] : 0;
    sm[t] = v;
    __syncthreads();
#pragma unroll
    for (int o = 1; o < 128; o <<= 1) {
        int x = (t >= o) ? sm[t - o] : 0;
        __syncthreads();
        sm[t] += x;
        __syncthreads();
    }
    if (t < nb) g_boff[t] = sm[t] - v;          // exclusive block offsets
    if (t == 127) g_off[Ntot] = sm[127];        // total = E
}

__global__ void k_scan3(int Ntot) {
    const int i = blockIdx.x * blockDim.x + threadIdx.x;
    if (i < Ntot) {
        int v = g_offt[i] + g_boff[i / SCB];
        g_off[i] = v;
        g_pos[i] = v;
    }
}

__global__ void k_scatter(const int* __restrict__ ei, int E) {
    const int e = blockIdx.x * blockDim.x + threadIdx.x;
    if (e >= E) return;
    const int s = __ldg(ei + e);
    const int d = __ldg(ei + E + e);
    float4 as = *(const float4*)(g_asrc + s * NH);
    float4 ad = *(const float4*)(g_adst + d * NH);
    float4 w;
    w.x = __expf(lrelu(as.x + ad.x, SLOPE_ATT));
    w.y = __expf(lrelu(as.y + ad.y, SLOPE_ATT));
    w.z = __expf(lrelu(as.z + ad.z, SLOPE_ATT));
    w.w = __expf(lrelu(as.w + ad.w, SLOPE_ATT));
    const int slot = atomicAdd(&g_pos[d], 1);
    g_esrc[slot] = s;
    g_ew[slot]   = w;
}

// ---------------------------------------------------------------------------
// K5: pull-mode aggregation — one warp per node, NO atomics.
// Lane l owns channels [l*4,+4) (heads 0/1) and [128+l*4,+4) (heads 2/3):
// each gather LDG.128 is warp-contiguous (4 lines). Denominator summed in
// registers; normalize+bias+lrelu fused; one coalesced row write.
// ---------------------------------------------------------------------------
__global__ void __launch_bounds__(256) k_node_agg(const float* __restrict__ bias,
                                                  int Ntot) {
    const int n    = (blockIdx.x * blockDim.x + threadIdx.x) >> 5;
    const int lane = threadIdx.x & 31;
    if (n >= Ntot) return;

    const int hlo = lane >> 4;        // 0 or 1
    const int hhi = hlo + 2;          // 2 or 3

    // self-loop weights
    float es0 = __expf(lrelu(g_asrc[n * NH + hlo] + g_adst[n * NH + hlo], SLOPE_ATT));
    float es1 = __expf(lrelu(g_asrc[n * NH + hhi] + g_adst[n * NH + hhi], SLOPE_ATT));

    const float* hn = g_h + (size_t)n * HC + lane * 4;
    float4 h0 = *(const float4*)(hn);
    float4 h1 = *(const float4*)(hn + 128);

    float4 acc0 = make_float4(h0.x * es0, h0.y * es0, h0.z * es0, h0.w * es0);
    float4 acc1 = make_float4(h1.x * es1, h1.y * es1, h1.z * es1, h1.w * es1);
    float den0 = es0, den1 = es1;

    const int beg = g_off[n];
    const int end = g_off[n + 1];

    int    s  = 0;
    float4 w4 = make_float4(0.f, 0.f, 0.f, 0.f);
    if (beg < end) { s = g_esrc[beg]; w4 = g_ew[beg]; }

    for (int i = beg; i < end; i++) {
        int    sn = 0;
        float4 wn = make_float4(0.f, 0.f, 0.f, 0.f);
        if (i + 1 < end) { sn = g_esrc[i + 1]; wn = g_ew[i + 1]; }

        const float e0 = (lane < 16) ? w4.x : w4.y;
        const float e1 = (lane < 16) ? w4.z : w4.w;

        const float* sp = g_h + (size_t)s * HC + lane * 4;
        float4 v0 = *(const float4*)(sp);
        float4 v1 = *(const float4*)(sp + 128);

        acc0.x += v0.x * e0; acc0.y += v0.y * e0;
        acc0.z += v0.z * e0; acc0.w += v0.w * e0;
        acc1.x += v1.x * e1; acc1.y += v1.y * e1;
        acc1.z += v1.z * e1; acc1.w += v1.w * e1;
        den0 += e0; den1 += e1;

        s = sn; w4 = wn;
    }

    const float inv0 = 1.0f / den0;
    const float inv1 = 1.0f / den1;
    const float4 b0 = *(const float4*)(bias + lane * 4);
    const float4 b1 = *(const float4*)(bias + 128 + lane * 4);

    float4 o0 = make_float4(lrelu(acc0.x * inv0 + b0.x, SLOPE_ACT),
                            lrelu(acc0.y * inv0 + b0.y, SLOPE_ACT),
                            lrelu(acc0.z * inv0 + b0.z, SLOPE_ACT),
                            lrelu(acc0.w * inv0 + b0.w, SLOPE_ACT));
    float4 o1 = make_float4(lrelu(acc1.x * inv1 + b1.x, SLOPE_ACT),
                            lrelu(acc1.y * inv1 + b1.y, SLOPE_ACT),
                            lrelu(acc1.z * inv1 + b1.z, SLOPE_ACT),
                            lrelu(acc1.w * inv1 + b1.w, SLOPE_ACT));

    float* op = g_o + (size_t)n * HC + lane * 4;
    *(float4*)(op)       = o0;
    *(float4*)(op + 128) = o1;
}

// ---------------------------------------------------------------------------
// K6: segmented mean-pool over sorted batch (run-length flush; rows already
// finalized by k_node_agg)
// ---------------------------------------------------------------------------
__global__ void __launch_bounds__(256) k_node_pool(const int* __restrict__ batch,
                                                   int Ntot) {
    __shared__ int sb[RPB];

    const int n0 = blockIdx.x * RPB;
    if (n0 >= Ntot) return;
    const int t = threadIdx.x;
    const int cnt_local = min(RPB, Ntot - n0);

    if (t < cnt_local) sb[t] = batch[n0 + t];
    __syncthreads();

    float acc = 0.0f;
    int   cur = sb[0];
    int   run = 0;

    float cv = g_o[(size_t)n0 * HC + t];
    for (int i = 0; i < cnt_local; i++) {
        float nv = 0.0f;
        if (i + 1 < cnt_local)
            nv = g_o[(size_t)(n0 + i + 1) * HC + t];

        const int bn = sb[i];
        if (bn != cur) {
            atomicAdd(&g_pool[(size_t)cur * HC + t], acc);
            if (t == 0) atomicAdd(&g_cnt[cur], (float)run);
            acc = 0.0f; run = 0; cur = bn;
        }
        acc += cv;
        run++;
        cv = nv;
    }
    atomicAdd(&g_pool[(size_t)cur * HC + t], acc);
    if (t == 0) atomicAdd(&g_cnt[cur], (float)run);
}

// ---------------------------------------------------------------------------
// K7: final GEMM  out[G,768] = (pool/cnt) @ fc1_w + fc1_b
// ---------------------------------------------------------------------------
__global__ void __launch_bounds__(256) k_final(const float* __restrict__ fw,
                                               const float* __restrict__ fb,
                                               float* __restrict__ out, int G) {
    __shared__ float p[16][HC];
    const int g0 = blockIdx.x * 16;
    const int j0 = blockIdx.y * 128;
    const int t  = threadIdx.x;

    for (int i = t; i < 16 * HC; i += 256) {
        const int g = i / HC, k = i % HC;
        float val = 0.0f;
        if (g0 + g < G) {
            float c = fmaxf(g_cnt[g0 + g], 1.0f);
            val = g_pool[(size_t)(g0 + g) * HC + k] / c;
        }
        p[g][k] = val;
    }
    __syncthreads();

    const int j  = j0 + (t & 127);
    const int gg = t >> 7;
    float acc[8];
#pragma unroll
    for (int r = 0; r < 8; r++) acc[r] = 0.0f;

    for (int k = 0; k < HC; k++) {
        float wv = fw[(size_t)k * NOUT + j];
#pragma unroll
        for (int r = 0; r < 8; r++) acc[r] += p[gg + r * 2][k] * wv;
    }
    float bv = fb[j];
#pragma unroll
    for (int r = 0; r < 8; r++) {
        const int g = g0 + gg + r * 2;
        if (g < G) out[(size_t)g * NOUT + j] = acc[r] + bv;
    }
}

// ---------------------------------------------------------------------------
// launch
// ---------------------------------------------------------------------------
extern "C" void kernel_launch(void* const* d_in, const int* in_sizes, int n_in,
                              void* d_out, int out_size) {
    const float* x       = (const float*)d_in[0];
    const int*   ei      = (const int*)d_in[1];
    const int*   batch   = (const int*)d_in[2];
    const float* lin_w   = (const float*)d_in[3];
    const float* att_src = (const float*)d_in[4];
    const float* att_dst = (const float*)d_in[5];
    const float* bias    = (const float*)d_in[6];
    const float* fc1_w   = (const float*)d_in[7];
    const float* fc1_b   = (const float*)d_in[8];
    float* out = (float*)d_out;

    const int N = in_sizes[0] / NIN;
    const int E = in_sizes[1] / 2;
    const int G = out_size / NOUT;
    const int nb = (N + SCB - 1) / SCB;

    const int zeroElems = (G * HC > N) ? G * HC : N;
    k_zero<<<(zeroElems + 255) / 256, 256>>>(G, N);

    dim3 gemm_grid((N + 127) / 128, HC / 128);
    k_gemm_feat<<<gemm_grid, 256>>>(x, lin_w, N);

    // CSR build (independent of GEMM output except scatter needs a-values)
    k_count<<<(E + 255) / 256, 256>>>(ei, E);
    k_scan1<<<nb, SCB>>>(N);
    k_scan2<<<1, 128>>>(nb, N);
    k_scan3<<<(N + 255) / 256, 256>>>(N);

    k_node_att<<<(N + 7) / 8, 256>>>(att_src, att_dst, N);
    k_scatter<<<(E + 255) / 256, 256>>>(ei, E);

    k_node_agg<<<(N + 7) / 8, 256>>>(bias, N);
    k_node_pool<<<(N + RPB - 1) / RPB, 256>>>(batch, N);

    dim3 fin_grid((G + 15) / 16, NOUT / 128);
    k_final<<<fin_grid, 256>>>(fc1_w, fc1_b, out, G);
}

// round 10
// speedup vs baseline: 1.8246x; 1.0687x over previous
#include <cuda_runtime.h>
#include <cuda_bf16.h>

// ---------------------------------------------------------------------------
// Problem constants
// ---------------------------------------------------------------------------
#define NH    4          // heads
#define CH    64         // channels per head
#define HC    256        // NH*CH
#define NIN   300
#define NOUT  768
#define MAXN  50048
#define MAXE  800000
#define MAXG  1024
#define SLOPE_ATT 0.2f
#define SLOPE_ACT 0.01f
#define RPB   64         // nodes per block in pooling kernel
#define SCB   512        // scan block size

// ---------------------------------------------------------------------------
// Scratch (device globals; no allocation allowed)
// ---------------------------------------------------------------------------
__device__ uint4  g_hb4[MAXN * HC / 8];  // h in bf16 [N, HC] (uint4-aligned)
__device__ float  g_o[MAXN * HC];        // finalized node output [N, HC]
__device__ float  g_asrc[MAXN * NH];     // atomic-accumulated logit partials
__device__ float  g_adst[MAXN * NH];
__device__ int    g_cntn[MAXN];          // per-destination edge counts
__device__ int    g_off[MAXN + 1];       // CSR offsets
__device__ int    g_offt[MAXN];          // per-block-scan temp
__device__ int    g_pos[MAXN];           // running slot counters
__device__ int    g_bsum[128];
__device__ int    g_boff[128];
__device__ int    g_esrc[MAXE];          // CSR: source node per slot
__device__ float4 g_ew[MAXE];            // CSR: per-head weights per slot
__device__ float  g_pool[MAXG * HC];
__device__ float  g_cnt[MAXG];

// ---------------------------------------------------------------------------
// Helpers
// ---------------------------------------------------------------------------
__device__ __forceinline__ float lrelu(float v, float s) { return v > 0.0f ? v : s * v; }

__device__ __forceinline__ unsigned long long pack2(float lo, float hi) {
    unsigned long long r;
    asm("mov.b64 %0, {%1, %2};" : "=l"(r) : "f"(lo), "f"(hi));
    return r;
}
__device__ __forceinline__ float2 unpack2(unsigned long long v) {
    float2 f;
    asm("mov.b64 {%0, %1}, %2;" : "=f"(f.x), "=f"(f.y) : "l"(v));
    return f;
}
__device__ __forceinline__ void ffma2(unsigned long long& acc,
                                      unsigned long long a, unsigned long long b) {
    asm("fma.rn.f32x2 %0, %1, %2, %0;" : "+l"(acc) : "l"(a), "l"(b));
}
__device__ __forceinline__ unsigned bf2u(__nv_bfloat162 v) {
    unsigned u; __builtin_memcpy(&u, &v, 4); return u;
}
__device__ __forceinline__ float2 u2f2(unsigned u) {
    __nv_bfloat162 b; __builtin_memcpy(&b, &u, 4);
    return __bfloat1622float2(b);
}

// ---------------------------------------------------------------------------
// K1: h = x @ lin_w — 128x128 tile, BK=8, f32x2 FMAs.
// Epilogue: bf16 store of h + attention-logit partials (exact fp32 dots,
// 8-lane shfl reduction, atomicAdd into g_asrc/g_adst).
// ---------------------------------------------------------------------------
__global__ void __launch_bounds__(256) k_gemm_feat(const float* __restrict__ x,
                                                   const float* __restrict__ w,
                                                   const float* __restrict__ att_src,
                                                   const float* __restrict__ att_dst,
                                                   int Ntot) {
    __shared__ float As[8][128];
    __shared__ float Bs[8][128];

    const int t  = threadIdx.x;
    const int m0 = blockIdx.x * 128;
    const int n0 = blockIdx.y * 128;
    const int tx = t & 15;
    const int ty = t >> 4;

    const int lm = t >> 1;
    const int lv = t & 1;
    const int kin = t >> 5;
    const int c4  = t & 31;

    unsigned long long acc[8][4];
#pragma unroll
    for (int i = 0; i < 8; i++)
#pragma unroll
        for (int j = 0; j < 4; j++) acc[i][j] = 0ull;

    const int nk = (NIN + 7) / 8;    // 38

    float4 ra, rb;
    {
        const int k = lv * 4;
        const int m = m0 + lm;
        ra = make_float4(0.f, 0.f, 0.f, 0.f);
        if (m < Ntot) {
            if (k + 3 < NIN) ra = *(const float4*)(x + (size_t)m * NIN + k);
        }
        rb = make_float4(0.f, 0.f, 0.f, 0.f);
        if (kin < NIN) rb = *(const float4*)(w + (size_t)kin * HC + n0 + c4 * 4);
    }

    for (int kt = 0; kt < nk; kt++) {
        __syncthreads();
        As[lv * 4 + 0][lm] = ra.x;
        As[lv * 4 + 1][lm] = ra.y;
        As[lv * 4 + 2][lm] = ra.z;
        As[lv * 4 + 3][lm] = ra.w;
        ((float4*)&Bs[kin][0])[c4] = rb;
        __syncthreads();

        if (kt + 1 < nk) {
            const int k0 = (kt + 1) * 8;
            const int ka = k0 + lv * 4;
            const int m  = m0 + lm;
            ra = make_float4(0.f, 0.f, 0.f, 0.f);
            if (m < Ntot) {
                if (ka + 3 < NIN) {
                    ra = *(const float4*)(x + (size_t)m * NIN + ka);
                } else {
                    float* rv = &ra.x;
#pragma unroll
                    for (int j = 0; j < 4; j++)
                        if (ka + j < NIN) rv[j] = x[(size_t)m * NIN + ka + j];
                }
            }
            const int kb = k0 + kin;
            rb = make_float4(0.f, 0.f, 0.f, 0.f);
            if (kb < NIN) rb = *(const float4*)(w + (size_t)kb * HC + n0 + c4 * 4);
        }

#pragma unroll
        for (int k = 0; k < 8; k++) {
            float4 a0 = *(const float4*)&As[k][ty * 8];
            float4 a1 = *(const float4*)&As[k][ty * 8 + 4];
            float4 b0 = *(const float4*)&Bs[k][tx * 8];
            float4 b1 = *(const float4*)&Bs[k][tx * 8 + 4];
            unsigned long long bp[4] = {pack2(b0.x, b0.y), pack2(b0.z, b0.w),
                                        pack2(b1.x, b1.y), pack2(b1.z, b1.w)};
            float am[8] = {a0.x, a0.y, a0.z, a0.w, a1.x, a1.y, a1.z, a1.w};
#pragma unroll
            for (int i = 0; i < 8; i++) {
                unsigned long long ap = pack2(am[i], am[i]);
#pragma unroll
                for (int j = 0; j < 4; j++) ffma2(acc[i][j], ap, bp[j]);
            }
        }
    }

    // ---------------- epilogue: bf16 store + attention partials ----------------
    const int colg = n0 + tx * 8;            // global col base (within one head)
    const int head = colg >> 6;              // 0..3
    const float4 s0 = *(const float4*)(att_src + colg);
    const float4 s1 = *(const float4*)(att_src + colg + 4);
    const float4 d0 = *(const float4*)(att_dst + colg);
    const float4 d1 = *(const float4*)(att_dst + colg + 4);
    __nv_bfloat16* hb = (__nv_bfloat16*)g_hb4;

#pragma unroll
    for (int i = 0; i < 8; i++) {
        const int m = m0 + ty * 8 + i;
        float2 c01 = unpack2(acc[i][0]);
        float2 c23 = unpack2(acc[i][1]);
        float2 c45 = unpack2(acc[i][2]);
        float2 c67 = unpack2(acc[i][3]);
        float4 h0 = make_float4(c01.x, c01.y, c23.x, c23.y);
        float4 h1 = make_float4(c45.x, c45.y, c67.x, c67.y);

        float ps = h0.x * s0.x + h0.y * s0.y + h0.z * s0.z + h0.w * s0.w +
                   h1.x * s1.x + h1.y * s1.y + h1.z * s1.z + h1.w * s1.w;
        float pd = h0.x * d0.x + h0.y * d0.y + h0.z * d0.z + h0.w * d0.w +
                   h1.x * d1.x + h1.y * d1.y + h1.z * d1.z + h1.w * d1.w;
#pragma unroll
        for (int msk = 1; msk < 8; msk <<= 1) {
            ps += __shfl_xor_sync(0xffffffffu, ps, msk);
            pd += __shfl_xor_sync(0xffffffffu, pd, msk);
        }

        if (m < Ntot) {
            uint4 pk;
            pk.x = bf2u(__floats2bfloat162_rn(h0.x, h0.y));
            pk.y = bf2u(__floats2bfloat162_rn(h0.z, h0.w));
            pk.z = bf2u(__floats2bfloat162_rn(h1.x, h1.y));
            pk.w = bf2u(__floats2bfloat162_rn(h1.z, h1.w));
            *(uint4*)(hb + (size_t)m * HC + colg) = pk;
            if ((tx & 7) == 0) {
                atomicAdd(&g_asrc[m * NH + head], ps);
                atomicAdd(&g_adst[m * NH + head], pd);
            }
        }
    }
}

// ---------------------------------------------------------------------------
// K0: zero accumulators (pool, counts, per-dst counters, logit partials)
// ---------------------------------------------------------------------------
__global__ void k_zero(int Gtot, int Ntot) {
    const int i = blockIdx.x * blockDim.x + threadIdx.x;
    if (i < Gtot * HC) g_pool[i] = 0.0f;
    if (i < Gtot) g_cnt[i] = 0.0f;
    if (i < Ntot) g_cntn[i] = 0;
    if (i < Ntot * NH) { g_asrc[i] = 0.0f; g_adst[i] = 0.0f; }
}

// ---------------------------------------------------------------------------
// CSR build: count -> scan(3) -> scatter
// ---------------------------------------------------------------------------
__global__ void k_count(const int* __restrict__ ei, int E) {
    const int e = blockIdx.x * blockDim.x + threadIdx.x;
    if (e < E) atomicAdd(&g_cntn[ei[E + e]], 1);
}

__global__ void __launch_bounds__(SCB) k_scan1(int Ntot) {
    __shared__ int sm[SCB];
    const int t = threadIdx.x;
    const int i = blockIdx.x * SCB + t;
    int v = (i < Ntot) ? g_cntn[i] : 0;
    sm[t] = v;
    __syncthreads();
#pragma unroll
    for (int o = 1; o < SCB; o <<= 1) {
        int x = (t >= o) ? sm[t - o] : 0;
        __syncthreads();
        sm[t] += x;
        __syncthreads();
    }
    if (i < Ntot) g_offt[i] = sm[t] - v;        // exclusive within block
    if (t == SCB - 1) g_bsum[blockIdx.x] = sm[t];
}

__global__ void __launch_bounds__(128) k_scan2(int nb, int Ntot) {
    __shared__ int sm[128];
    const int t = threadIdx.x;
    int v = (t < nb) ? g_bsum[t] : 0;
    sm[t] = v;
    __syncthreads();
#pragma unroll
    for (int o = 1; o < 128; o <<= 1) {
        int x = (t >= o) ? sm[t - o] : 0;
        __syncthreads();
        sm[t] += x;
        __syncthreads();
    }
    if (t < nb) g_boff[t] = sm[t] - v;          // exclusive block offsets
    if (t == 127) g_off[Ntot] = sm[127];        // total = E
}

__global__ void k_scan3(int Ntot) {
    const int i = blockIdx.x * blockDim.x + threadIdx.x;
    if (i < Ntot) {
        int v = g_offt[i] + g_boff[i / SCB];
        g_off[i] = v;
        g_pos[i] = v;
    }
}

__global__ void k_scatter(const int* __restrict__ ei, int E) {
    const int e = blockIdx.x * blockDim.x + threadIdx.x;
    if (e >= E) return;
    const int s = __ldg(ei + e);
    const int d = __ldg(ei + E + e);
    float4 as = *(const float4*)(g_asrc + s * NH);
    float4 ad = *(const float4*)(g_adst + d * NH);
    float4 w;
    w.x = __expf(lrelu(as.x + ad.x, SLOPE_ATT));
    w.y = __expf(lrelu(as.y + ad.y, SLOPE_ATT));
    w.z = __expf(lrelu(as.z + ad.z, SLOPE_ATT));
    w.w = __expf(lrelu(as.w + ad.w, SLOPE_ATT));
    const int slot = atomicAdd(&g_pos[d], 1);
    g_esrc[slot] = s;
    g_ew[slot]   = w;
}

// ---------------------------------------------------------------------------
// K5: pull-mode aggregation — one warp per node, NO atomics, bf16 gather.
// Lane l owns channels [l*4,+4) (heads 0/1) and [128+l*4,+4) (heads 2/3).
// bf16 row = 512 B -> each gather wavefront covers 2 cache lines.
// ---------------------------------------------------------------------------
__global__ void __launch_bounds__(256) k_node_agg(const float* __restrict__ bias,
                                                  int Ntot) {
    const int n    = (blockIdx.x * blockDim.x + threadIdx.x) >> 5;
    const int lane = threadIdx.x & 31;
    if (n >= Ntot) return;

    const int hlo = lane >> 4;        // 0 or 1
    const int hhi = hlo + 2;          // 2 or 3

    // self-loop weights (exact fp32 logits)
    float es0 = __expf(lrelu(g_asrc[n * NH + hlo] + g_adst[n * NH + hlo], SLOPE_ATT));
    float es1 = __expf(lrelu(g_asrc[n * NH + hhi] + g_adst[n * NH + hhi], SLOPE_ATT));

    const uint2* hb = (const uint2*)g_hb4;   // 1 uint2 = 4 bf16 channels
    {
        // nothing; loads below
    }
    uint2 su0 = hb[(size_t)n * 64 + lane];        // ch [lane*4, +4)
    uint2 su1 = hb[(size_t)n * 64 + 32 + lane];   // ch [128+lane*4, +4)
    float2 a = u2f2(su0.x), b = u2f2(su0.y);
    float2 c = u2f2(su1.x), d = u2f2(su1.y);

    float4 acc0 = make_float4(a.x * es0, a.y * es0, b.x * es0, b.y * es0);
    float4 acc1 = make_float4(c.x * es1, c.y * es1, d.x * es1, d.y * es1);
    float den0 = es0, den1 = es1;

    const int beg = g_off[n];
    const int end = g_off[n + 1];

    int    s  = 0;
    float4 w4 = make_float4(0.f, 0.f, 0.f, 0.f);
    if (beg < end) { s = g_esrc[beg]; w4 = g_ew[beg]; }

    for (int i = beg; i < end; i++) {
        int    sn = 0;
        float4 wn = make_float4(0.f, 0.f, 0.f, 0.f);
        if (i + 1 < end) { sn = g_esrc[i + 1]; wn = g_ew[i + 1]; }

        const float e0 = (lane < 16) ? w4.x : w4.y;
        const float e1 = (lane < 16) ? w4.z : w4.w;

        uint2 u0 = hb[(size_t)s * 64 + lane];
        uint2 u1 = hb[(size_t)s * 64 + 32 + lane];
        float2 v0 = u2f2(u0.x), v1 = u2f2(u0.y);
        float2 v2 = u2f2(u1.x), v3 = u2f2(u1.y);

        acc0.x += v0.x * e0; acc0.y += v0.y * e0;
        acc0.z += v1.x * e0; acc0.w += v1.y * e0;
        acc1.x += v2.x * e1; acc1.y += v2.y * e1;
        acc1.z += v3.x * e1; acc1.w += v3.y * e1;
        den0 += e0; den1 += e1;

        s = sn; w4 = wn;
    }

    const float inv0 = 1.0f / den0;
    const float inv1 = 1.0f / den1;
    const float4 b0 = *(const float4*)(bias + lane * 4);
    const float4 b1 = *(const float4*)(bias + 128 + lane * 4);

    float4 o0 = make_float4(lrelu(acc0.x * inv0 + b0.x, SLOPE_ACT),
                            lrelu(acc0.y * inv0 + b0.y, SLOPE_ACT),
                            lrelu(acc0.z * inv0 + b0.z, SLOPE_ACT),
                            lrelu(acc0.w * inv0 + b0.w, SLOPE_ACT));
    float4 o1 = make_float4(lrelu(acc1.x * inv1 + b1.x, SLOPE_ACT),
                            lrelu(acc1.y * inv1 + b1.y, SLOPE_ACT),
                            lrelu(acc1.z * inv1 + b1.z, SLOPE_ACT),
                            lrelu(acc1.w * inv1 + b1.w, SLOPE_ACT));

    float* op = g_o + (size_t)n * HC + lane * 4;
    *(float4*)(op)       = o0;
    *(float4*)(op + 128) = o1;
}

// ---------------------------------------------------------------------------
// K6: segmented mean-pool over sorted batch (run-length flush)
// ---------------------------------------------------------------------------
__global__ void __launch_bounds__(256) k_node_pool(const int* __restrict__ batch,
                                                   int Ntot) {
    __shared__ int sb[RPB];

    const int n0 = blockIdx.x * RPB;
    if (n0 >= Ntot) return;
    const int t = threadIdx.x;
    const int cnt_local = min(RPB, Ntot - n0);

    if (t < cnt_local) sb[t] = batch[n0 + t];
    __syncthreads();

    float acc = 0.0f;
    int   cur = sb[0];
    int   run = 0;

    float cv = g_o[(size_t)n0 * HC + t];
    for (int i = 0; i < cnt_local; i++) {
        float nv = 0.0f;
        if (i + 1 < cnt_local)
            nv = g_o[(size_t)(n0 + i + 1) * HC + t];

        const int bn = sb[i];
        if (bn != cur) {
            atomicAdd(&g_pool[(size_t)cur * HC + t], acc);
            if (t == 0) atomicAdd(&g_cnt[cur], (float)run);
            acc = 0.0f; run = 0; cur = bn;
        }
        acc += cv;
        run++;
        cv = nv;
    }
    atomicAdd(&g_pool[(size_t)cur * HC + t], acc);
    if (t == 0) atomicAdd(&g_cnt[cur], (float)run);
}

// ---------------------------------------------------------------------------
// K7: final GEMM  out[G,768] = (pool/cnt) @ fc1_w + fc1_b
// ---------------------------------------------------------------------------
__global__ void __launch_bounds__(256) k_final(const float* __restrict__ fw,
                                               const float* __restrict__ fb,
                                               float* __restrict__ out, int G) {
    __shared__ float p[16][HC];
    const int g0 = blockIdx.x * 16;
    const int j0 = blockIdx.y * 128;
    const int t  = threadIdx.x;

    for (int i = t; i < 16 * HC; i += 256) {
        const int g = i / HC, k = i % HC;
        float val = 0.0f;
        if (g0 + g < G) {
            float c = fmaxf(g_cnt[g0 + g], 1.0f);
            val = g_pool[(size_t)(g0 + g) * HC + k] / c;
        }
        p[g][k] = val;
    }
    __syncthreads();

    const int j  = j0 + (t & 127);
    const int gg = t >> 7;
    float acc[8];
#pragma unroll
    for (int r = 0; r < 8; r++) acc[r] = 0.0f;

    for (int k = 0; k < HC; k++) {
        float wv = fw[(size_t)k * NOUT + j];
#pragma unroll
        for (int r = 0; r < 8; r++) acc[r] += p[gg + r * 2][k] * wv;
    }
    float bv = fb[j];
#pragma unroll
    for (int r = 0; r < 8; r++) {
        const int g = g0 + gg + r * 2;
        if (g < G) out[(size_t)g * NOUT + j] = acc[r] + bv;
    }
}

// ---------------------------------------------------------------------------
// launch
// ---------------------------------------------------------------------------
extern "C" void kernel_launch(void* const* d_in, const int* in_sizes, int n_in,
                              void* d_out, int out_size) {
    const float* x       = (const float*)d_in[0];
    const int*   ei      = (const int*)d_in[1];
    const int*   batch   = (const int*)d_in[2];
    const float* lin_w   = (const float*)d_in[3];
    const float* att_src = (const float*)d_in[4];
    const float* att_dst = (const float*)d_in[5];
    const float* bias    = (const float*)d_in[6];
    const float* fc1_w   = (const float*)d_in[7];
    const float* fc1_b   = (const float*)d_in[8];
    float* out = (float*)d_out;

    const int N = in_sizes[0] / NIN;
    const int E = in_sizes[1] / 2;
    const int G = out_size / NOUT;
    const int nb = (N + SCB - 1) / SCB;

    const int zeroElems = (G * HC > N * NH) ? G * HC : N * NH;
    k_zero<<<(zeroElems + 255) / 256, 256>>>(G, N);

    // CSR counting/scan is independent of the GEMM output
    k_count<<<(E + 255) / 256, 256>>>(ei, E);
    k_scan1<<<nb, SCB>>>(N);
    k_scan2<<<1, 128>>>(nb, N);
    k_scan3<<<(N + 255) / 256, 256>>>(N);

    dim3 gemm_grid((N + 127) / 128, HC / 128);
    k_gemm_feat<<<gemm_grid, 256>>>(x, lin_w, att_src, att_dst, N);

    k_scatter<<<(E + 255) / 256, 256>>>(ei, E);
    k_node_agg<<<(N + 7) / 8, 256>>>(bias, N);
    k_node_pool<<<(N + RPB - 1) / RPB, 256>>>(batch, N);

    dim3 fin_grid((G + 15) / 16, NOUT / 128);
    k_final<<<fin_grid, 256>>>(fc1_w, fc1_b, out, G);
}

// round 11
// speedup vs baseline: 2.6129x; 1.4321x over previous
#include <cuda_runtime.h>
#include <cuda_bf16.h>

// ---------------------------------------------------------------------------
// Problem constants
// ---------------------------------------------------------------------------
#define NH    4          // heads
#define CH    64         // channels per head
#define HC    256        // NH*CH
#define NIN   300
#define NOUT  768
#define MAXN  50048
#define MAXE  800000
#define MAXG  1024
#define SLOPE_ATT 0.2f
#define SLOPE_ACT 0.01f
#define RPB   64         // nodes per block in pooling kernel
#define SCB   512        // scan block size

// ---------------------------------------------------------------------------
// Scratch (device globals; no allocation allowed)
// ---------------------------------------------------------------------------
__device__ uint4  g_hb4[MAXN * HC / 8];  // h in bf16 [N, HC] (uint4-aligned)
__device__ float  g_o[MAXN * HC];        // finalized node output [N, HC]
__device__ float  g_asrc[MAXN * NH];     // attention logits (plain stores)
__device__ float  g_adst[MAXN * NH];
__device__ int    g_cntn[MAXN];          // per-destination edge counts
__device__ int    g_off[MAXN + 1];       // CSR offsets
__device__ int    g_offt[MAXN];          // per-block-scan temp
__device__ int    g_pos[MAXN];           // running slot counters
__device__ int    g_bsum[128];
__device__ int    g_boff[128];
__device__ int    g_esrc[MAXE];          // CSR: source node per slot
__device__ float4 g_ew[MAXE];            // CSR: per-head weights per slot
__device__ float  g_pool[MAXG * HC];
__device__ float  g_cnt[MAXG];

// ---------------------------------------------------------------------------
// Helpers
// ---------------------------------------------------------------------------
__device__ __forceinline__ float lrelu(float v, float s) { return v > 0.0f ? v : s * v; }

__device__ __forceinline__ unsigned bf2u(__nv_bfloat162 v) {
    unsigned u; __builtin_memcpy(&u, &v, 4); return u;
}
__device__ __forceinline__ float2 u2f2(unsigned u) {
    __nv_bfloat162 b; __builtin_memcpy(&b, &u, 4);
    return __bfloat1622float2(b);
}

__device__ __forceinline__ void ldsm4(unsigned* r, unsigned addr) {
    asm volatile("ldmatrix.sync.aligned.m8n8.x4.shared.b16 {%0,%1,%2,%3}, [%4];"
                 : "=r"(r[0]), "=r"(r[1]), "=r"(r[2]), "=r"(r[3]) : "r"(addr));
}
__device__ __forceinline__ void ldsm4t(unsigned* r, unsigned addr) {
    asm volatile("ldmatrix.sync.aligned.m8n8.x4.trans.shared.b16 {%0,%1,%2,%3}, [%4];"
                 : "=r"(r[0]), "=r"(r[1]), "=r"(r[2]), "=r"(r[3]) : "r"(addr));
}
__device__ __forceinline__ void mma16816(float* c, const unsigned* a,
                                         unsigned b0, unsigned b1) {
    asm volatile("mma.sync.aligned.m16n8k16.row.col.f32.bf16.bf16.f32 "
                 "{%0,%1,%2,%3}, {%4,%5,%6,%7}, {%8,%9}, {%0,%1,%2,%3};"
                 : "+f"(c[0]), "+f"(c[1]), "+f"(c[2]), "+f"(c[3])
                 : "r"(a[0]), "r"(a[1]), "r"(a[2]), "r"(a[3]), "r"(b0), "r"(b1));
}

// ---------------------------------------------------------------------------
// K1: h = x @ lin_w on tensor cores (bf16 HMMA, 3-term hi/lo split).
// 128x256 tile, BK=16, 512 threads, warp tile 32x64 (warp-col == head).
// Fused epilogue: attention logits (plain stores) + staged bf16 h write.
// ---------------------------------------------------------------------------
#define ASTR 24    // A smem row stride in halfs (48 B)
#define BSTR 264   // B smem row stride in halfs (528 B)

__global__ void __launch_bounds__(512, 1)
k_gemm_mma(const float* __restrict__ x, const float* __restrict__ w,
           const float* __restrict__ att_src, const float* __restrict__ att_dst,
           int Ntot) {
    __shared__ __align__(16) char smem_raw[33792];
    __nv_bfloat16* sA_hi = (__nv_bfloat16*)(smem_raw);            // 128*24*2 = 6144
    __nv_bfloat16* sA_lo = (__nv_bfloat16*)(smem_raw + 6144);
    __nv_bfloat16* sB_hi = (__nv_bfloat16*)(smem_raw + 12288);    // 16*264*2 = 8448
    __nv_bfloat16* sB_lo = (__nv_bfloat16*)(smem_raw + 20736);

    const int t    = threadIdx.x;
    const int lane = t & 31;
    const int wid  = t >> 5;
    const int wm   = wid >> 2;       // 0..3 : row block of 32
    const int wn   = wid & 3;        // 0..3 : col block of 64 == head
    const int m0   = blockIdx.x * 128;

    // global-load mappings
    const int arow = t >> 2;         // 0..127
    const int akq  = (t & 3) * 4;    // 0,4,8,12
    const int bkr  = t >> 5;         // 0..15
    const int bc   = (t & 31) * 8;   // 0..248

    float acc[2][8][4];
#pragma unroll
    for (int f = 0; f < 2; f++)
#pragma unroll
        for (int j = 0; j < 8; j++)
#pragma unroll
            for (int q = 0; q < 4; q++) acc[f][j][q] = 0.0f;

    // ldmatrix addresses (fixed per lane)
    const unsigned baseAhi = (unsigned)__cvta_generic_to_shared(sA_hi);
    const unsigned baseAlo = (unsigned)__cvta_generic_to_shared(sA_lo);
    const unsigned baseBhi = (unsigned)__cvta_generic_to_shared(sB_hi);
    const unsigned baseBlo = (unsigned)__cvta_generic_to_shared(sB_lo);
    unsigned aAhi[2], aAlo[2], aBhi[4], aBlo[4];
    {
        const int ar  = (lane & 15);
        const int ach = (lane >> 4) * 8;
#pragma unroll
        for (int f = 0; f < 2; f++) {
            const int off = ((wm * 32 + f * 16 + ar) * ASTR + ach) * 2;
            aAhi[f] = baseAhi + off;
            aAlo[f] = baseAlo + off;
        }
        const int mat  = lane >> 3;
        const int bkrw = (lane & 7) + ((mat & 1) << 3);
        const int bnof = (mat >> 1) * 8;
#pragma unroll
        for (int p = 0; p < 4; p++) {
            const int off = (bkrw * BSTR + wn * 64 + p * 16 + bnof) * 2;
            aBhi[p] = baseBhi + off;
            aBlo[p] = baseBlo + off;
        }
    }

    const int nk = 19;               // ceil(300/16)
    float4 ra, rb0, rb1;

    // prefetch tile 0
    {
        ra = make_float4(0.f, 0.f, 0.f, 0.f);
        const int m = m0 + arow;
        if (m < Ntot && akq + 3 < NIN)
            ra = *(const float4*)(x + (size_t)m * NIN + akq);
        rb0 = make_float4(0.f, 0.f, 0.f, 0.f);
        rb1 = make_float4(0.f, 0.f, 0.f, 0.f);
        if (bkr < NIN) {
            rb0 = *(const float4*)(w + (size_t)bkr * HC + bc);
            rb1 = *(const float4*)(w + (size_t)bkr * HC + bc + 4);
        }
    }

    for (int kt = 0; kt < nk; kt++) {
        __syncthreads();
        // store prefetched tile (fp32 -> bf16 hi/lo)
        {
            float av[4] = {ra.x, ra.y, ra.z, ra.w};
            __nv_bfloat16 hi[4], lo[4];
#pragma unroll
            for (int q = 0; q < 4; q++) {
                hi[q] = __float2bfloat16_rn(av[q]);
                lo[q] = __float2bfloat16_rn(av[q] - __bfloat162float(hi[q]));
            }
            uint2 uh, ul;
            uh.x = bf2u(__nv_bfloat162{hi[0], hi[1]});
            uh.y = bf2u(__nv_bfloat162{hi[2], hi[3]});
            ul.x = bf2u(__nv_bfloat162{lo[0], lo[1]});
            ul.y = bf2u(__nv_bfloat162{lo[2], lo[3]});
            *(uint2*)(sA_hi + arow * ASTR + akq) = uh;
            *(uint2*)(sA_lo + arow * ASTR + akq) = ul;

            float bv[8] = {rb0.x, rb0.y, rb0.z, rb0.w, rb1.x, rb1.y, rb1.z, rb1.w};
            __nv_bfloat16 bh[8], blo[8];
#pragma unroll
            for (int q = 0; q < 8; q++) {
                bh[q]  = __float2bfloat16_rn(bv[q]);
                blo[q] = __float2bfloat16_rn(bv[q] - __bfloat162float(bh[q]));
            }
            uint4 vh, vl;
            vh.x = bf2u(__nv_bfloat162{bh[0], bh[1]});
            vh.y = bf2u(__nv_bfloat162{bh[2], bh[3]});
            vh.z = bf2u(__nv_bfloat162{bh[4], bh[5]});
            vh.w = bf2u(__nv_bfloat162{bh[6], bh[7]});
            vl.x = bf2u(__nv_bfloat162{blo[0], blo[1]});
            vl.y = bf2u(__nv_bfloat162{blo[2], blo[3]});
            vl.z = bf2u(__nv_bfloat162{blo[4], blo[5]});
            vl.w = bf2u(__nv_bfloat162{blo[6], blo[7]});
            *(uint4*)(sB_hi + bkr * BSTR + bc) = vh;
            *(uint4*)(sB_lo + bkr * BSTR + bc) = vl;
        }
        __syncthreads();

        // prefetch next tile
        if (kt + 1 < nk) {
            const int kb = (kt + 1) * 16;
            ra = make_float4(0.f, 0.f, 0.f, 0.f);
            const int m = m0 + arow;
            const int ka = kb + akq;
            if (m < Ntot && ka + 3 < NIN)
                ra = *(const float4*)(x + (size_t)m * NIN + ka);
            rb0 = make_float4(0.f, 0.f, 0.f, 0.f);
            rb1 = make_float4(0.f, 0.f, 0.f, 0.f);
            const int kw = kb + bkr;
            if (kw < NIN) {
                rb0 = *(const float4*)(w + (size_t)kw * HC + bc);
                rb1 = *(const float4*)(w + (size_t)kw * HC + bc + 4);
            }
        }

        // compute: 3-term split MMAs
        unsigned a_hi[2][4], a_lo[2][4];
#pragma unroll
        for (int f = 0; f < 2; f++) {
            ldsm4(a_hi[f], aAhi[f]);
            ldsm4(a_lo[f], aAlo[f]);
        }
#pragma unroll
        for (int p = 0; p < 4; p++) {
            unsigned bh[4];
            ldsm4t(bh, aBhi[p]);
#pragma unroll
            for (int f = 0; f < 2; f++) {
                mma16816(acc[f][2 * p],     a_hi[f], bh[0], bh[1]);
                mma16816(acc[f][2 * p + 1], a_hi[f], bh[2], bh[3]);
                mma16816(acc[f][2 * p],     a_lo[f], bh[0], bh[1]);
                mma16816(acc[f][2 * p + 1], a_lo[f], bh[2], bh[3]);
            }
            unsigned bl[4];
            ldsm4t(bl, aBlo[p]);
#pragma unroll
            for (int f = 0; f < 2; f++) {
                mma16816(acc[f][2 * p],     a_hi[f], bl[0], bl[1]);
                mma16816(acc[f][2 * p + 1], a_hi[f], bl[2], bl[3]);
            }
        }
    }

    // ---------------- epilogue: attention logits (plain stores) ----------------
    const int nb = wn * 64;
    const int qc = (lane & 3) * 2;
    float2 sv[8], dv[8];
#pragma unroll
    for (int j = 0; j < 8; j++) {
        sv[j] = *(const float2*)(att_src + nb + j * 8 + qc);
        dv[j] = *(const float2*)(att_dst + nb + j * 8 + qc);
    }
#pragma unroll
    for (int f = 0; f < 2; f++) {
        float ps0 = 0.f, pd0 = 0.f, ps1 = 0.f, pd1 = 0.f;
#pragma unroll
        for (int j = 0; j < 8; j++) {
            ps0 += acc[f][j][0] * sv[j].x + acc[f][j][1] * sv[j].y;
            pd0 += acc[f][j][0] * dv[j].x + acc[f][j][1] * dv[j].y;
            ps1 += acc[f][j][2] * sv[j].x + acc[f][j][3] * sv[j].y;
            pd1 += acc[f][j][2] * dv[j].x + acc[f][j][3] * dv[j].y;
        }
#pragma unroll
        for (int msk = 1; msk < 4; msk <<= 1) {
            ps0 += __shfl_xor_sync(0xffffffffu, ps0, msk);
            pd0 += __shfl_xor_sync(0xffffffffu, pd0, msk);
            ps1 += __shfl_xor_sync(0xffffffffu, ps1, msk);
            pd1 += __shfl_xor_sync(0xffffffffu, pd1, msk);
        }
        const int r0 = m0 + wm * 32 + f * 16 + (lane >> 2);
        const int r1 = r0 + 8;
        if ((lane & 3) == 0) {
            if (r0 < Ntot) { g_asrc[r0 * NH + wn] = ps0; g_adst[r0 * NH + wn] = pd0; }
            if (r1 < Ntot) { g_asrc[r1 * NH + wn] = ps1; g_adst[r1 * NH + wn] = pd1; }
        }
    }

    // ---------------- epilogue: staged bf16 h store (coalesced) ----------------
    unsigned* stg = (unsigned*)smem_raw;   // 64 rows x 132 uints (= 264 halfs)
#pragma unroll
    for (int half = 0; half < 2; half++) {
        __syncthreads();
        if ((wm >> 1) == half) {
            const int srb = (wm & 1) * 32;
#pragma unroll
            for (int f = 0; f < 2; f++) {
                const int sr0 = srb + f * 16 + (lane >> 2);
#pragma unroll
                for (int j = 0; j < 8; j++) {
                    const int cu = (nb >> 1) + j * 4 + (lane & 3);
                    stg[sr0 * 132 + cu] =
                        bf2u(__floats2bfloat162_rn(acc[f][j][0], acc[f][j][1]));
                    stg[(sr0 + 8) * 132 + cu] =
                        bf2u(__floats2bfloat162_rn(acc[f][j][2], acc[f][j][3]));
                }
            }
        }
        __syncthreads();
        const int r  = t >> 3;
        const int gr = m0 + half * 64 + r;
        if (gr < Ntot) {
            const uint4* srow = (const uint4*)(stg + r * 132);
            uint4* drow = g_hb4 + (size_t)gr * 32;
#pragma unroll
            for (int i = 0; i < 4; i++) {
                const int c4 = (t & 7) + i * 8;
                drow[c4] = srow[c4];
            }
        }
    }
}

// ---------------------------------------------------------------------------
// K0: zero accumulators (pool, counts, per-dst counters)
// ---------------------------------------------------------------------------
__global__ void k_zero(int Gtot, int Ntot) {
    const int i = blockIdx.x * blockDim.x + threadIdx.x;
    if (i < Gtot * HC) g_pool[i] = 0.0f;
    if (i < Gtot) g_cnt[i] = 0.0f;
    if (i < Ntot) g_cntn[i] = 0;
}

// ---------------------------------------------------------------------------
// CSR build: count -> scan(3) -> scatter
// ---------------------------------------------------------------------------
__global__ void k_count(const int* __restrict__ ei, int E) {
    const int e = blockIdx.x * blockDim.x + threadIdx.x;
    if (e < E) atomicAdd(&g_cntn[ei[E + e]], 1);
}

__global__ void __launch_bounds__(SCB) k_scan1(int Ntot) {
    __shared__ int sm[SCB];
    const int t = threadIdx.x;
    const int i = blockIdx.x * SCB + t;
    int v = (i < Ntot) ? g_cntn[i] : 0;
    sm[t] = v;
    __syncthreads();
#pragma unroll
    for (int o = 1; o < SCB; o <<= 1) {
        int x = (t >= o) ? sm[t - o] : 0;
        __syncthreads();
        sm[t] += x;
        __syncthreads();
    }
    if (i < Ntot) g_offt[i] = sm[t] - v;
    if (t == SCB - 1) g_bsum[blockIdx.x] = sm[t];
}

__global__ void __launch_bounds__(128) k_scan2(int nb, int Ntot) {
    __shared__ int sm[128];
    const int t = threadIdx.x;
    int v = (t < nb) ? g_bsum[t] : 0;
    sm[t] = v;
    __syncthreads();
#pragma unroll
    for (int o = 1; o < 128; o <<= 1) {
        int x = (t >= o) ? sm[t - o] : 0;
        __syncthreads();
        sm[t] += x;
        __syncthreads();
    }
    if (t < nb) g_boff[t] = sm[t] - v;
    if (t == 127) g_off[Ntot] = sm[127];
}

__global__ void k_scan3(int Ntot) {
    const int i = blockIdx.x * blockDim.x + threadIdx.x;
    if (i < Ntot) {
        int v = g_offt[i] + g_boff[i / SCB];
        g_off[i] = v;
        g_pos[i] = v;
    }
}

__global__ void k_scatter(const int* __restrict__ ei, int E) {
    const int e = blockIdx.x * blockDim.x + threadIdx.x;
    if (e >= E) return;
    const int s = __ldg(ei + e);
    const int d = __ldg(ei + E + e);
    float4 as = *(const float4*)(g_asrc + s * NH);
    float4 ad = *(const float4*)(g_adst + d * NH);
    float4 wv;
    wv.x = __expf(lrelu(as.x + ad.x, SLOPE_ATT));
    wv.y = __expf(lrelu(as.y + ad.y, SLOPE_ATT));
    wv.z = __expf(lrelu(as.z + ad.z, SLOPE_ATT));
    wv.w = __expf(lrelu(as.w + ad.w, SLOPE_ATT));
    const int slot = atomicAdd(&g_pos[d], 1);
    g_esrc[slot] = s;
    g_ew[slot]   = wv;
}

// ---------------------------------------------------------------------------
// K5: pull-mode aggregation — one warp per node, no atomics, bf16 gather,
// edge loop unrolled x2 (two independent row gathers in flight).
// ---------------------------------------------------------------------------
__global__ void __launch_bounds__(256) k_node_agg(const float* __restrict__ bias,
                                                  int Ntot) {
    const int n    = (blockIdx.x * blockDim.x + threadIdx.x) >> 5;
    const int lane = threadIdx.x & 31;
    if (n >= Ntot) return;

    const int hlo = lane >> 4;
    const int hhi = hlo + 2;

    float es0 = __expf(lrelu(g_asrc[n * NH + hlo] + g_adst[n * NH + hlo], SLOPE_ATT));
    float es1 = __expf(lrelu(g_asrc[n * NH + hhi] + g_adst[n * NH + hhi], SLOPE_ATT));

    const uint2* hb = (const uint2*)g_hb4;
    uint2 su0 = hb[(size_t)n * 64 + lane];
    uint2 su1 = hb[(size_t)n * 64 + 32 + lane];
    float2 fa = u2f2(su0.x), fb = u2f2(su0.y);
    float2 fc = u2f2(su1.x), fd = u2f2(su1.y);

    float4 acc0 = make_float4(fa.x * es0, fa.y * es0, fb.x * es0, fb.y * es0);
    float4 acc1 = make_float4(fc.x * es1, fc.y * es1, fd.x * es1, fd.y * es1);
    float den0 = es0, den1 = es1;

    const int beg = g_off[n];
    const int end = g_off[n + 1];

    int i = beg;
    for (; i + 2 <= end; i += 2) {
        const int sA = g_esrc[i];
        const int sB = g_esrc[i + 1];
        const float4 wA = g_ew[i];
        const float4 wB = g_ew[i + 1];

        uint2 uA0 = hb[(size_t)sA * 64 + lane];
        uint2 uA1 = hb[(size_t)sA * 64 + 32 + lane];
        uint2 uB0 = hb[(size_t)sB * 64 + lane];
        uint2 uB1 = hb[(size_t)sB * 64 + 32 + lane];

        const float eA0 = (lane < 16) ? wA.x : wA.y;
        const float eA1 = (lane < 16) ? wA.z : wA.w;
        const float eB0 = (lane < 16) ? wB.x : wB.y;
        const float eB1 = (lane < 16) ? wB.z : wB.w;

        float2 v0 = u2f2(uA0.x), v1 = u2f2(uA0.y);
        float2 v2 = u2f2(uA1.x), v3 = u2f2(uA1.y);
        acc0.x += v0.x * eA0; acc0.y += v0.y * eA0;
        acc0.z += v1.x * eA0; acc0.w += v1.y * eA0;
        acc1.x += v2.x * eA1; acc1.y += v2.y * eA1;
        acc1.z += v3.x * eA1; acc1.w += v3.y * eA1;

        v0 = u2f2(uB0.x); v1 = u2f2(uB0.y);
        v2 = u2f2(uB1.x); v3 = u2f2(uB1.y);
        acc0.x += v0.x * eB0; acc0.y += v0.y * eB0;
        acc0.z += v1.x * eB0; acc0.w += v1.y * eB0;
        acc1.x += v2.x * eB1; acc1.y += v2.y * eB1;
        acc1.z += v3.x * eB1; acc1.w += v3.y * eB1;

        den0 += eA0 + eB0; den1 += eA1 + eB1;
    }
    if (i < end) {
        const int sA = g_esrc[i];
        const float4 wA = g_ew[i];
        uint2 uA0 = hb[(size_t)sA * 64 + lane];
        uint2 uA1 = hb[(size_t)sA * 64 + 32 + lane];
        const float eA0 = (lane < 16) ? wA.x : wA.y;
        const float eA1 = (lane < 16) ? wA.z : wA.w;
        float2 v0 = u2f2(uA0.x), v1 = u2f2(uA0.y);
        float2 v2 = u2f2(uA1.x), v3 = u2f2(uA1.y);
        acc0.x += v0.x * eA0; acc0.y += v0.y * eA0;
        acc0.z += v1.x * eA0; acc0.w += v1.y * eA0;
        acc1.x += v2.x * eA1; acc1.y += v2.y * eA1;
        acc1.z += v3.x * eA1; acc1.w += v3.y * eA1;
        den0 += eA0; den1 += eA1;
    }

    const float inv0 = 1.0f / den0;
    const float inv1 = 1.0f / den1;
    const float4 bb0 = *(const float4*)(bias + lane * 4);
    const float4 bb1 = *(const float4*)(bias + 128 + lane * 4);

    float4 o0 = make_float4(lrelu(acc0.x * inv0 + bb0.x, SLOPE_ACT),
                            lrelu(acc0.y * inv0 + bb0.y, SLOPE_ACT),
                            lrelu(acc0.z * inv0 + bb0.z, SLOPE_ACT),
                            lrelu(acc0.w * inv0 + bb0.w, SLOPE_ACT));
    float4 o1 = make_float4(lrelu(acc1.x * inv1 + bb1.x, SLOPE_ACT),
                            lrelu(acc1.y * inv1 + bb1.y, SLOPE_ACT),
                            lrelu(acc1.z * inv1 + bb1.z, SLOPE_ACT),
                            lrelu(acc1.w * inv1 + bb1.w, SLOPE_ACT));

    float* op = g_o + (size_t)n * HC + lane * 4;
    *(float4*)(op)       = o0;
    *(float4*)(op + 128) = o1;
}

// ---------------------------------------------------------------------------
// K6: segmented mean-pool over sorted batch (run-length flush)
// ---------------------------------------------------------------------------
__global__ void __launch_bounds__(256) k_node_pool(const int* __restrict__ batch,
                                                   int Ntot) {
    __shared__ int sb[RPB];

    const int n0 = blockIdx.x * RPB;
    if (n0 >= Ntot) return;
    const int t = threadIdx.x;
    const int cnt_local = min(RPB, Ntot - n0);

    if (t < cnt_local) sb[t] = batch[n0 + t];
    __syncthreads();

    float acc = 0.0f;
    int   cur = sb[0];
    int   run = 0;

    float cv = g_o[(size_t)n0 * HC + t];
    for (int i = 0; i < cnt_local; i++) {
        float nv = 0.0f;
        if (i + 1 < cnt_local)
            nv = g_o[(size_t)(n0 + i + 1) * HC + t];

        const int bn = sb[i];
        if (bn != cur) {
            atomicAdd(&g_pool[(size_t)cur * HC + t], acc);
            if (t == 0) atomicAdd(&g_cnt[cur], (float)run);
            acc = 0.0f; run = 0; cur = bn;
        }
        acc += cv;
        run++;
        cv = nv;
    }
    atomicAdd(&g_pool[(size_t)cur * HC + t], acc);
    if (t == 0) atomicAdd(&g_cnt[cur], (float)run);
}

// ---------------------------------------------------------------------------
// K7: final GEMM  out[G,768] = (pool/cnt) @ fc1_w + fc1_b
// ---------------------------------------------------------------------------
__global__ void __launch_bounds__(256) k_final(const float* __restrict__ fw,
                                               const float* __restrict__ fb,
                                               float* __restrict__ out, int G) {
    __shared__ float p[16][HC];
    const int g0 = blockIdx.x * 16;
    const int j0 = blockIdx.y * 128;
    const int t  = threadIdx.x;

    for (int i = t; i < 16 * HC; i += 256) {
        const int g = i / HC, k = i % HC;
        float val = 0.0f;
        if (g0 + g < G) {
            float c = fmaxf(g_cnt[g0 + g], 1.0f);
            val = g_pool[(size_t)(g0 + g) * HC + k] / c;
        }
        p[g][k] = val;
    }
    __syncthreads();

    const int j  = j0 + (t & 127);
    const int gg = t >> 7;
    float acc[8];
#pragma unroll
    for (int r = 0; r < 8; r++) acc[r] = 0.0f;

    for (int k = 0; k < HC; k++) {
        float wv = fw[(size_t)k * NOUT + j];
#pragma unroll
        for (int r = 0; r < 8; r++) acc[r] += p[gg + r * 2][k] * wv;
    }
    float bv = fb[j];
#pragma unroll
    for (int r = 0; r < 8; r++) {
        const int g = g0 + gg + r * 2;
        if (g < G) out[(size_t)g * NOUT + j] = acc[r] + bv;
    }
}

// ---------------------------------------------------------------------------
// launch
// ---------------------------------------------------------------------------
extern "C" void kernel_launch(void* const* d_in, const int* in_sizes, int n_in,
                              void* d_out, int out_size) {
    const float* x       = (const float*)d_in[0];
    const int*   ei      = (const int*)d_in[1];
    const int*   batch   = (const int*)d_in[2];
    const float* lin_w   = (const float*)d_in[3];
    const float* att_src = (const float*)d_in[4];
    const float* att_dst = (const float*)d_in[5];
    const float* bias    = (const float*)d_in[6];
    const float* fc1_w   = (const float*)d_in[7];
    const float* fc1_b   = (const float*)d_in[8];
    float* out = (float*)d_out;

    const int N = in_sizes[0] / NIN;
    const int E = in_sizes[1] / 2;
    const int G = out_size / NOUT;
    const int nb = (N + SCB - 1) / SCB;

    const int zeroElems = (G * HC > N) ? G * HC : N;
    k_zero<<<(zeroElems + 255) / 256, 256>>>(G, N);

    k_count<<<(E + 255) / 256, 256>>>(ei, E);
    k_scan1<<<nb, SCB>>>(N);
    k_scan2<<<1, 128>>>(nb, N);
    k_scan3<<<(N + 255) / 256, 256>>>(N);

    k_gemm_mma<<<(N + 127) / 128, 512>>>(x, lin_w, att_src, att_dst, N);

    k_scatter<<<(E + 255) / 256, 256>>>(ei, E);
    k_node_agg<<<(N + 7) / 8, 256>>>(bias, N);
    k_node_pool<<<(N + RPB - 1) / RPB, 256>>>(batch, N);

    dim3 fin_grid((G + 15) / 16, NOUT / 128);
    k_final<<<fin_grid, 256>>>(fc1_w, fc1_b, out, G);
}